// round 12
// baseline (speedup 1.0000x reference)
#include <cuda_runtime.h>
#include <cuda_fp16.h>
#include <math.h>
#include <stdint.h>

#define BZ 4
#define LZ 2048
#define WD 2048
#define NHD 32
#define HDM 64
#define MBSZ 16
#define NMBC 128
#define EPSC 1e-6f
#define ELEMS (BZ*LZ*WD)
#define KP 4096            // split-fp16 A: [hi | lo]
#define NROWS_B 4224       // 2048 q + 2048 v + 32 lr + 96 pad (33*128)

// ---------------- scratch (device globals; no allocation) ----------------
__device__ float g_xq[ELEMS];
__device__ float g_xv[ELEMS];
__device__ float g_scan[ELEMS];
__device__ float g_lrraw[8192 * 32];
__device__ __half g_A_hf[(size_t)8192 * KP];       // [hi | lo]
__device__ __half g_B_hf[(size_t)NROWS_B * 2048];  // hi plane only (dedup)

// ---------------- PTX helpers ----------------
__device__ __forceinline__ uint32_t smem_u32(const void* p) {
    uint32_t a;
    asm("{ .reg .u64 t; cvta.to.shared.u64 t, %1; cvt.u32.u64 %0, t; }" : "=r"(a) : "l"(p));
    return a;
}
#define CPA16(d, s) asm volatile("cp.async.cg.shared.global [%0], [%1], 16;" :: "r"(d), "l"(s) : "memory")
#define CPA4(d, s)  asm volatile("cp.async.ca.shared.global [%0], [%1], 4;"  :: "r"(d), "l"(s) : "memory")
#define CPA_COMMIT() asm volatile("cp.async.commit_group;" ::: "memory")
#define CPA_WAIT0()  asm volatile("cp.async.wait_group 0;" ::: "memory")

__device__ __forceinline__ void ldsm_x4(uint32_t a, uint32_t& r0, uint32_t& r1, uint32_t& r2, uint32_t& r3) {
    asm volatile("ldmatrix.sync.aligned.m8n8.x4.shared.b16 {%0,%1,%2,%3}, [%4];"
                 : "=r"(r0), "=r"(r1), "=r"(r2), "=r"(r3) : "r"(a));
}
__device__ __forceinline__ void mma_f16(float* c, const uint32_t* a, const uint32_t* b) {
    asm volatile("mma.sync.aligned.m16n8k16.row.col.f32.f16.f16.f32 "
                 "{%0,%1,%2,%3}, {%4,%5,%6,%7}, {%8,%9}, {%0,%1,%2,%3};"
                 : "+f"(c[0]), "+f"(c[1]), "+f"(c[2]), "+f"(c[3])
                 : "r"(a[0]), "r"(a[1]), "r"(a[2]), "r"(a[3]), "r"(b[0]), "r"(b[1]));
}

// ---------------- split-fp16 helpers ----------------
__device__ __forceinline__ void splitf16(const float4& v, uint2& hi, uint2& lo) {
    __half2 h01 = __floats2half2_rn(v.x, v.y);
    __half2 h23 = __floats2half2_rn(v.z, v.w);
    float2 f01 = __half22float2(h01), f23 = __half22float2(h23);
    __half2 l01 = __floats2half2_rn(v.x - f01.x, v.y - f01.y);
    __half2 l23 = __floats2half2_rn(v.z - f23.x, v.w - f23.y);
    hi.x = *(uint32_t*)&h01; hi.y = *(uint32_t*)&h23;
    lo.x = *(uint32_t*)&l01; lo.y = *(uint32_t*)&l23;
}

// ---------------- A conversion: fp32 [8192,2048] -> fp16 [8192,4096] = [hi|lo] ----------------
__global__ __launch_bounds__(256) void ttt_cvtA(const float* __restrict__ src)
{
    int t = blockIdx.x * 256 + threadIdx.x;
    float4 v = ((const float4*)src)[t];
    int r = t >> 9, c4 = t & 511;
    size_t base = (size_t)r * KP + (c4 << 2);
    uint2 hi, lo;
    splitf16(v, hi, lo);
    *(uint2*)(g_A_hf + base)        = hi;
    *(uint2*)(g_A_hf + base + 2048) = lo;
}

// ---------------- B conversion (3 sources + zero pad): hi plane only ----------------
__global__ __launch_bounds__(256) void ttt_cvtB(const float* __restrict__ w0,
                                                const float* __restrict__ w1,
                                                const float* __restrict__ w2)
{
    int row = blockIdx.x;
    int tid = threadIdx.x;
    const float* srcp = nullptr;
    if (row < 2048) srcp = w0 + (size_t)row * 2048;
    else if (row < 4096) srcp = w1 + (size_t)(row - 2048) * 2048;
    else if (row < 4128) srcp = w2 + (size_t)(row - 4096) * 2048;
    float4 v0 = make_float4(0, 0, 0, 0), v1 = v0;
    if (srcp) { v0 = ((const float4*)srcp)[tid]; v1 = ((const float4*)srcp)[tid + 256]; }
    uint2 hi, lo;
    splitf16(v0, hi, lo);
    *(uint2*)(g_B_hf + (size_t)row * 2048 + (tid << 2)) = hi;
    splitf16(v1, hi, lo);
    *(uint2*)(g_B_hf + (size_t)row * 2048 + ((tid + 256) << 2)) = hi;
}

// ---------------- fp16 mma.sync GEMM: 128x128, 256 thr, B-dedup, 2-stage x 48KB ----------------
#define GS_STAGE 49152
#define GKSTEPS 32
__global__ __launch_bounds__(256, 2) void ttt_hgemm(float* Cext, int fused)
{
    extern __shared__ char smem[];
    uint32_t sb = smem_u32(smem);
    const int tid = threadIdx.x;
    const int wid = tid >> 5, lane = tid & 31;
    const int m0 = blockIdx.y << 7;
    const int n0 = blockIdx.x << 7;
    const int mw = (wid >> 2) << 6;
    const int nw = (wid & 3) << 5;

    const __half* Ab = g_A_hf + (size_t)m0 * KP;
    const __half* Bb = g_B_hf + (size_t)n0 * 2048;

    float acc[4][4][4];
#pragma unroll
    for (int i = 0; i < 4; i++)
#pragma unroll
        for (int j = 0; j < 4; j++)
#pragma unroll
            for (int q = 0; q < 4; q++) acc[i][j][q] = 0.0f;

    auto load_stage = [&](int s, int kt) {
        uint32_t sAh = sb + s * GS_STAGE;
        uint32_t sAl = sAh + 16384;
        uint32_t sB  = sAh + 32768;
#pragma unroll
        for (int i = 0; i < 4; i++) {
            int idx = tid + (i << 8);
            int row = idx >> 3, c = idx & 7;
            uint32_t soff = (uint32_t)(row << 7) + (((uint32_t)(c ^ (row & 7))) << 4);
            const __half* ar = Ab + (size_t)row * KP + kt * 64 + c * 8;
            CPA16(sAh + soff, (const char*)ar);
            CPA16(sAl + soff, (const char*)(ar + 2048));
            CPA16(sB + soff, (const char*)(Bb + (size_t)row * 2048 + kt * 64 + c * 8));
        }
        CPA_COMMIT();
    };

    load_stage(0, 0);
    const int lr15 = lane & 15, lhi = lane >> 4;

    for (int kt = 0; kt < GKSTEPS; kt++) {
        int s = kt & 1;
        if (kt + 1 < GKSTEPS) {
            load_stage(s ^ 1, kt + 1);
            asm volatile("cp.async.wait_group 1;" ::: "memory");
        } else {
            CPA_WAIT0();
        }
        __syncthreads();

        uint32_t aH = sb + s * GS_STAGE;
        uint32_t aL = aH + 16384;
        uint32_t bB = aH + 32768;
#pragma unroll
        for (int ks = 0; ks < 4; ks++) {
            uint32_t bf[4][2];
#pragma unroll
            for (int np = 0; np < 2; np++) {
                int row = nw + np * 16 + lr15;
                uint32_t bd = bB + (uint32_t)(row << 7) + ((uint32_t)((2 * ks + lhi) ^ (row & 7)) << 4);
                uint32_t r0, r1, r2, r3;
                ldsm_x4(bd, r0, r1, r2, r3);
                bf[np * 2][0] = r0;     bf[np * 2][1] = r2;
                bf[np * 2 + 1][0] = r1; bf[np * 2 + 1][1] = r3;
            }
            uint32_t af[4][4];
#pragma unroll
            for (int mt = 0; mt < 4; mt++) {
                int row = mw + mt * 16 + lr15;
                uint32_t ad = aH + (uint32_t)(row << 7) + ((uint32_t)((2 * ks + lhi) ^ (row & 7)) << 4);
                ldsm_x4(ad, af[mt][0], af[mt][1], af[mt][2], af[mt][3]);
            }
#pragma unroll
            for (int mt = 0; mt < 4; mt++)
#pragma unroll
                for (int nt = 0; nt < 4; nt++)
                    mma_f16(acc[mt][nt], af[mt], bf[nt]);
#pragma unroll
            for (int mt = 0; mt < 4; mt++) {
                int row = mw + mt * 16 + lr15;
                uint32_t ad = aL + (uint32_t)(row << 7) + ((uint32_t)((2 * ks + lhi) ^ (row & 7)) << 4);
                ldsm_x4(ad, af[mt][0], af[mt][1], af[mt][2], af[mt][3]);
            }
#pragma unroll
            for (int mt = 0; mt < 4; mt++)
#pragma unroll
                for (int nt = 0; nt < 4; nt++)
                    mma_f16(acc[mt][nt], af[mt], bf[nt]);
        }
        __syncthreads();
    }

#pragma unroll
    for (int mt = 0; mt < 4; mt++) {
#pragma unroll
        for (int nt = 0; nt < 4; nt++) {
            int col = n0 + nw + nt * 8 + (lane & 3) * 2;
            int row = m0 + mw + mt * 16 + (lane >> 2);
            float2 va = make_float2(acc[mt][nt][0], acc[mt][nt][1]);
            float2 vb = make_float2(acc[mt][nt][2], acc[mt][nt][3]);
            if (!fused) {
                *(float2*)(Cext + (size_t)row * 2048 + col) = va;
                *(float2*)(Cext + (size_t)(row + 8) * 2048 + col) = vb;
            } else if (col < 2048) {
                *(float2*)(g_xq + (size_t)row * 2048 + col) = va;
                *(float2*)(g_xq + (size_t)(row + 8) * 2048 + col) = vb;
            } else if (col < 4096) {
                *(float2*)(g_xv + (size_t)row * 2048 + col - 2048) = va;
                *(float2*)(g_xv + (size_t)(row + 8) * 2048 + col - 2048) = vb;
            } else if (col < 4128) {
                *(float2*)(g_lrraw + (size_t)row * 32 + col - 4096) = va;
                *(float2*)(g_lrraw + (size_t)(row + 8) * 32 + col - 4096) = vb;
            }
        }
    }
}

// ---------------- TTT scan with fused causal-dwconv + RoPE + lr-sigmoid ----------------
// One block (256 thr) per (b,h). Prefetch raw xq rows (19x64), xv rows (16x64),
// and lr scalars via cp.async double-buffer; conv+rope computed in-kernel.
__global__ __launch_bounds__(256) void ttt_scan_kernel(
    const float* __restrict__ lt_idx,
    const float* __restrict__ lnw_g, const float* __restrict__ lnb_g,
    const float* __restrict__ W1g,   const float* __restrict__ b1g,
    const float* __restrict__ cqw,   const float* __restrict__ cqb,
    const float* __restrict__ ckw,   const float* __restrict__ ckb,
    const float* __restrict__ lrb)
{
    __shared__ float W1[64][64];
    __shared__ float sraw[2][19][68];
    __shared__ float sxv[2][16][68];
    __shared__ float sxq[16][68], sxk[16][68];
    __shared__ float grad[16][68], z[16][68];
    __shared__ float attn[16][16];
    __shared__ float wq_s[256], wk_s[256];
    __shared__ float bq_s[64], bk_s[64];
    __shared__ float b1[64], lnw[64], lnb[64];
    __shared__ float lrrawbuf[2][16], lr_sh[16], tok[16];

    int tid = threadIdx.x;
    int b = blockIdx.x >> 5, h = blockIdx.x & 31;
    const int ch0 = h * 64;

    for (int o = tid; o < 4096; o += 256)
        ((float*)W1)[o] = W1g[(size_t)h * 4096 + o];
    if (tid < 64) {
        b1[tid]  = b1g[h * 64 + tid];
        lnw[tid] = lnw_g[h * 64 + tid];
        lnb[tid] = lnb_g[h * 64 + tid];
        bq_s[tid] = cqb[ch0 + tid];
        bk_s[tid] = ckb[ch0 + tid];
    }
    wq_s[tid] = cqw[ch0 * 4 + tid];
    wk_s[tid] = ckw[ch0 * 4 + tid];
    if (tid < 16) tok[tid] = fmaxf(1.0f / (float)(tid + 1) + lt_idx[tid], 0.0f);
    // zero raw buffers (covers n=0 left pad rows)
    for (int o = tid; o < 2 * 19 * 68; o += 256)
        ((float*)sraw)[o] = 0.0f;

    const int warp = tid >> 5, lane = tid & 31;
    const int ii = tid >> 4;
    const int d0 = (tid & 15) * 4;
    const size_t base = ((size_t)b * LZ) * WD + (size_t)ch0;
    const float lrb_h = lrb[h];

    // per-thread RoPE registers: row = ii (pos = l%16 = row), pairs i0 = d0/2, i0+1
    float cs0, sn0, cs1, sn1;
    {
        int i0 = d0 >> 1;
        float inv0 = exp2f(-(float)i0 * (13.2877123795f / 32.0f));
        float inv1 = exp2f(-(float)(i0 + 1) * (13.2877123795f / 32.0f));
        sincosf((float)ii * inv0, &sn0, &cs0);
        sincosf((float)ii * inv1, &sn1, &cs1);
    }
    __syncthreads();   // zeroing + tables done before cp.async writes

    // smem addresses for cp.async
    const uint32_t a_raw = smem_u32(&sraw[0][0][0]);
    const uint32_t a_xv  = smem_u32(&sxv[0][0][0]);
    const uint32_t a_lrr = smem_u32(&lrrawbuf[0][0]);
    const uint32_t RAWB = 19 * 68 * 4;
    const uint32_t XVB  = 16 * 68 * 4;

    auto prefetch = [&](int s, int n) {
        // raw xq rows n*16-3 .. n*16+15 (19 rows x 64 floats)
#pragma unroll
        for (int it = 0; it < 2; it++) {
            int idx = tid + (it << 8);
            if (idx < 304) {
                int row = idx >> 4, c = idx & 15;
                int g = n * MBSZ - 3 + row;
                if (g >= 0)
                    CPA16(a_raw + s * RAWB + (uint32_t)(row * 272 + c * 16),
                          (const char*)&g_xq[base + (size_t)g * WD + c * 4]);
            }
        }
        // xv rows
        {
            int row = tid >> 4, c = tid & 15;
            CPA16(a_xv + s * XVB + (uint32_t)(row * 272 + c * 16),
                  (const char*)&g_xv[base + (size_t)(n * MBSZ + row) * WD + c * 4]);
        }
        // lr raw scalars
        if (tid < 16)
            CPA4(a_lrr + s * 64 + tid * 4,
                 (const char*)&g_lrraw[((size_t)b * LZ + n * MBSZ + tid) * 32 + h]);
        CPA_COMMIT();
    };

    prefetch(0, 0);

    for (int n = 0; n < NMBC; n++) {
        const int s = n & 1;
        CPA_WAIT0();
        __syncthreads();
        if (n + 1 < NMBC) prefetch(s ^ 1, n + 1);

        // conv + rope: thread (ii, d0) computes sxq/sxk row ii cols d0..d0+3
        {
            float4 t0 = *(const float4*)&sraw[s][ii + 0][d0];
            float4 t1 = *(const float4*)&sraw[s][ii + 1][d0];
            float4 t2 = *(const float4*)&sraw[s][ii + 2][d0];
            float4 t3 = *(const float4*)&sraw[s][ii + 3][d0];
            const float* ta = (const float*)&t0;
            const float* tb = (const float*)&t1;
            const float* tc = (const float*)&t2;
            const float* td = (const float*)&t3;
            float qv[4], kv[4];
#pragma unroll
            for (int d = 0; d < 4; d++) {
                int ch = d0 + d;
                qv[d] = bq_s[ch] + ta[d] * wq_s[ch * 4] + tb[d] * wq_s[ch * 4 + 1]
                                 + tc[d] * wq_s[ch * 4 + 2] + td[d] * wq_s[ch * 4 + 3];
                kv[d] = bk_s[ch] + ta[d] * wk_s[ch * 4] + tb[d] * wk_s[ch * 4 + 1]
                                 + tc[d] * wk_s[ch * 4 + 2] + td[d] * wk_s[ch * 4 + 3];
            }
            float4 oq, ok;
            oq.x = qv[0] * cs0 - qv[1] * sn0;  oq.y = qv[1] * cs0 + qv[0] * sn0;
            oq.z = qv[2] * cs1 - qv[3] * sn1;  oq.w = qv[3] * cs1 + qv[2] * sn1;
            ok.x = kv[0] * cs0 - kv[1] * sn0;  ok.y = kv[1] * cs0 + kv[0] * sn0;
            ok.z = kv[2] * cs1 - kv[3] * sn1;  ok.w = kv[3] * cs1 + kv[2] * sn1;
            *(float4*)&sxq[ii][d0] = oq;
            *(float4*)&sxk[ii][d0] = ok;
        }
        if (tid < 16)
            lr_sh[tid] = (1.0f / 64.0f) / (1.0f + expf(-(lrrawbuf[s][tid] + lrb_h)));
        __syncthreads();

        // Z1 = xk @ W1 + b1
        {
            float4 acc = *(const float4*)&b1[d0];
#pragma unroll 8
            for (int e = 0; e < 64; e++) {
                float xe = sxk[ii][e];
                float4 w = *(const float4*)&W1[e][d0];
                acc.x += xe * w.x; acc.y += xe * w.y; acc.z += xe * w.z; acc.w += xe * w.w;
            }
            *(float4*)&z[ii][d0] = acc;
        }
        // attn
        {
            int i = tid >> 4, j = tid & 15;
            float sa = 0.0f;
#pragma unroll 8
            for (int d = 0; d < 64; d++) sa += sxq[i][d] * sxk[j][d];
            attn[i][j] = sa;
        }
        __syncthreads();

        // grad = ln_l2_bwd(Z1, xv-xk)
        {
#pragma unroll
            for (int rr = 0; rr < 2; rr++) {
                int r = warp * 2 + rr;
                float x0 = z[r][lane], x1 = z[r][lane + 32];
                float sm = x0 + x1;
#pragma unroll
                for (int o = 16; o; o >>= 1) sm += __shfl_xor_sync(0xffffffffu, sm, o);
                float mu = sm * (1.0f / 64.0f);
                float e0 = x0 - mu, e1 = x1 - mu;
                float v = e0 * e0 + e1 * e1;
#pragma unroll
                for (int o = 16; o; o >>= 1) v += __shfl_xor_sync(0xffffffffu, v, o);
                float rstd = rsqrtf(v * (1.0f / 64.0f) + EPSC);
                float xh0 = e0 * rstd, xh1 = e1 * rstd;
                float t0 = sxv[s][r][lane] - sxk[r][lane];
                float t1 = sxv[s][r][lane + 32] - sxk[r][lane + 32];
                float gy0 = (lnw[lane] * xh0 + lnb[lane] - t0) * lnw[lane];
                float gy1 = (lnw[lane + 32] * xh1 + lnb[lane + 32] - t1) * lnw[lane + 32];
                float s1 = gy0 + gy1, s2 = gy0 * xh0 + gy1 * xh1;
#pragma unroll
                for (int o = 16; o; o >>= 1) {
                    s1 += __shfl_xor_sync(0xffffffffu, s1, o);
                    s2 += __shfl_xor_sync(0xffffffffu, s2, o);
                }
                float sc = rstd * (1.0f / 64.0f);
                grad[r][lane]      = (64.0f * gy0 - s1 - xh0 * s2) * sc;
                grad[r][lane + 32] = (64.0f * gy1 - s1 - xh1 * s2) * sc;
            }
        }
        __syncthreads();

        // Z1_bar
        {
            float4 acc = *(const float4*)&b1[d0];
#pragma unroll 8
            for (int e = 0; e < 64; e++) {
                float xe = sxq[ii][e];
                float4 w = *(const float4*)&W1[e][d0];
                acc.x += xe * w.x; acc.y += xe * w.y; acc.z += xe * w.z; acc.w += xe * w.w;
            }
            float tk = tok[ii];
            for (int j = 0; j <= ii; j++) {
                float cf = tk * lr_sh[j] * (attn[ii][j] + 1.0f);
                float4 gr = *(const float4*)&grad[j][d0];
                acc.x -= cf * gr.x; acc.y -= cf * gr.y; acc.z -= cf * gr.z; acc.w -= cf * gr.w;
            }
            *(float4*)&z[ii][d0] = acc;
        }
        __syncthreads();

        // out = xq + ln_fwd(Z1_bar)
        {
#pragma unroll
            for (int rr = 0; rr < 2; rr++) {
                int r = warp * 2 + rr;
                float x0 = z[r][lane], x1 = z[r][lane + 32];
                float sm = x0 + x1;
#pragma unroll
                for (int o = 16; o; o >>= 1) sm += __shfl_xor_sync(0xffffffffu, sm, o);
                float mu = sm * (1.0f / 64.0f);
                float e0 = x0 - mu, e1 = x1 - mu;
                float v = e0 * e0 + e1 * e1;
#pragma unroll
                for (int o = 16; o; o >>= 1) v += __shfl_xor_sync(0xffffffffu, v, o);
                float rstd = rsqrtf(v * (1.0f / 64.0f) + EPSC);
                size_t go = base + (size_t)(n * MBSZ + r) * WD;
                g_scan[go + lane]      = sxq[r][lane]      + lnw[lane] * (e0 * rstd)      + lnb[lane];
                g_scan[go + lane + 32] = sxq[r][lane + 32] + lnw[lane + 32] * (e1 * rstd) + lnb[lane + 32];
            }
        }

        // W1/b1 state update
        {
            float te = tok[15];
#pragma unroll
            for (int p = 0; p < 4; p++) {
                int d = ii * 4 + p;
                float4 acc = *(const float4*)&W1[d][d0];
#pragma unroll
                for (int j = 0; j < 16; j++) {
                    float cf = te * lr_sh[j] * sxk[j][d];
                    float4 gr = *(const float4*)&grad[j][d0];
                    acc.x -= cf * gr.x; acc.y -= cf * gr.y; acc.z -= cf * gr.z; acc.w -= cf * gr.w;
                }
                *(float4*)&W1[d][d0] = acc;
            }
            if (tid < 64) {
                float sm = 0.0f;
#pragma unroll
                for (int j = 0; j < 16; j++) sm += lr_sh[j] * grad[j][tid];
                b1[tid] -= te * sm;
            }
        }
        __syncthreads();
    }
}

// ---------------- post layer-norm fused with A split-fp16 conversion ----------------
__global__ __launch_bounds__(256) void ttt_postnorm_cvt(
    const float* __restrict__ pw, const float* __restrict__ pb)
{
    __shared__ float red[8];
    int bl = blockIdx.x, tid = threadIdx.x;
    int lane = tid & 31, warp = tid >> 5;
    const float4* src = (const float4*)(g_scan + (size_t)bl * WD);
    float4 v0 = src[tid], v1 = src[tid + 256];

    float s = v0.x + v0.y + v0.z + v0.w + v1.x + v1.y + v1.z + v1.w;
#pragma unroll
    for (int o = 16; o; o >>= 1) s += __shfl_xor_sync(0xffffffffu, s, o);
    if (lane == 0) red[warp] = s;
    __syncthreads();
    float tot = 0.0f;
#pragma unroll
    for (int i = 0; i < 8; i++) tot += red[i];
    float mu = tot * (1.0f / 2048.0f);
    __syncthreads();

    float q =
        (v0.x - mu) * (v0.x - mu) + (v0.y - mu) * (v0.y - mu) +
        (v0.z - mu) * (v0.z - mu) + (v0.w - mu) * (v0.w - mu) +
        (v1.x - mu) * (v1.x - mu) + (v1.y - mu) * (v1.y - mu) +
        (v1.z - mu) * (v1.z - mu) + (v1.w - mu) * (v1.w - mu);
#pragma unroll
    for (int o = 16; o; o >>= 1) q += __shfl_xor_sync(0xffffffffu, q, o);
    if (lane == 0) red[warp] = q;
    __syncthreads();
    float qt = 0.0f;
#pragma unroll
    for (int i = 0; i < 8; i++) qt += red[i];
    float rstd = rsqrtf(qt * (1.0f / 2048.0f) + EPSC);

    float4 w0 = ((const float4*)pw)[tid], w1 = ((const float4*)pw)[tid + 256];
    float4 b0 = ((const float4*)pb)[tid], b1v = ((const float4*)pb)[tid + 256];
    float4 o0, o1;
    o0.x = (v0.x - mu) * rstd * w0.x + b0.x;
    o0.y = (v0.y - mu) * rstd * w0.y + b0.y;
    o0.z = (v0.z - mu) * rstd * w0.z + b0.z;
    o0.w = (v0.w - mu) * rstd * w0.w + b0.w;
    o1.x = (v1.x - mu) * rstd * w1.x + b1v.x;
    o1.y = (v1.y - mu) * rstd * w1.y + b1v.y;
    o1.z = (v1.z - mu) * rstd * w1.z + b1v.z;
    o1.w = (v1.w - mu) * rstd * w1.w + b1v.w;

    size_t base0 = (size_t)bl * KP + (tid << 2);
    size_t base1 = (size_t)bl * KP + ((tid + 256) << 2);
    uint2 hi, lo;
    splitf16(o0, hi, lo);
    *(uint2*)(g_A_hf + base0)        = hi;
    *(uint2*)(g_A_hf + base0 + 2048) = lo;
    splitf16(o1, hi, lo);
    *(uint2*)(g_A_hf + base1)        = hi;
    *(uint2*)(g_A_hf + base1 + 2048) = lo;
}

// ---------------- launcher ----------------
extern "C" void kernel_launch(void* const* d_in, const int* in_sizes, int n_in,
                              void* d_out, int out_size)
{
    const float* hs  = (const float*)d_in[0];
    const float* q_w = (const float*)d_in[1];
    const float* v_w = (const float*)d_in[2];
    const float* o_w = (const float*)d_in[3];
    const float* cqw = (const float*)d_in[4];
    const float* cqb = (const float*)d_in[5];
    const float* ckw = (const float*)d_in[6];
    const float* ckb = (const float*)d_in[7];
    const float* lrw = (const float*)d_in[8];
    const float* lrb = (const float*)d_in[9];
    const float* lti = (const float*)d_in[10];
    const float* tnw = (const float*)d_in[11];
    const float* tnb = (const float*)d_in[12];
    const float* W1i = (const float*)d_in[13];
    const float* b1i = (const float*)d_in[14];
    const float* pnw = (const float*)d_in[15];
    const float* pnb = (const float*)d_in[16];
    float* out = (float*)d_out;

    static int smem_set = 0;
    if (!smem_set) {
        cudaFuncSetAttribute(ttt_hgemm, cudaFuncAttributeMaxDynamicSharedMemorySize, 2 * GS_STAGE);
        smem_set = 1;
    }

    // fused QV+lr projection: A=hs, B=[q_w; v_w; lr_w; pad]
    ttt_cvtA<<<16384, 256>>>(hs);
    ttt_cvtB<<<NROWS_B, 256>>>(q_w, v_w, lrw);
    ttt_hgemm<<<dim3(33, 64), 256, 2 * GS_STAGE>>>(nullptr, 1);   // -> g_xq, g_xv, g_lrraw

    // scan (conv+rope+lr fused inside)
    ttt_scan_kernel<<<BZ * NHD, 256>>>(lti, tnw, tnb, W1i, b1i, cqw, cqb, ckw, ckb, lrb);

    // B for final GEMM (stream-ordered after GEMM1 read g_B_hf)
    ttt_cvtB<<<2048, 256>>>(o_w, o_w, o_w);
    ttt_postnorm_cvt<<<BZ * LZ, 256>>>(pnw, pnb);                 // -> g_A_hf

    ttt_hgemm<<<dim3(16, 64), 256, 2 * GS_STAGE>>>(out, 0);
}

// round 13
// speedup vs baseline: 1.0226x; 1.0226x over previous
#include <cuda_runtime.h>
#include <cuda_fp16.h>
#include <math.h>
#include <stdint.h>

#define BZ 4
#define LZ 2048
#define WD 2048
#define NHD 32
#define HDM 64
#define MBSZ 16
#define NMBC 128
#define EPSC 1e-6f
#define ELEMS (BZ*LZ*WD)
#define KP 4096            // split-fp16 A: [hi | lo]
#define NROWS_B 4224       // 2048 q + 2048 v + 32 lr + 96 pad (33*128)

// ---------------- scratch (device globals; no allocation) ----------------
__device__ float g_xq[ELEMS];
__device__ float g_xv[ELEMS];
__device__ float g_scan[ELEMS];
__device__ float g_lrraw[8192 * 32];
__device__ __half g_A_hf[(size_t)8192 * KP];       // [hi | lo]
__device__ __half g_B_hf[(size_t)NROWS_B * 2048];  // hi plane only (dedup)

// ---------------- PTX helpers ----------------
__device__ __forceinline__ uint32_t smem_u32(const void* p) {
    uint32_t a;
    asm("{ .reg .u64 t; cvta.to.shared.u64 t, %1; cvt.u32.u64 %0, t; }" : "=r"(a) : "l"(p));
    return a;
}
#define CPA16(d, s) asm volatile("cp.async.cg.shared.global [%0], [%1], 16;" :: "r"(d), "l"(s) : "memory")
#define CPA4(d, s)  asm volatile("cp.async.ca.shared.global [%0], [%1], 4;"  :: "r"(d), "l"(s) : "memory")
#define CPA_COMMIT() asm volatile("cp.async.commit_group;" ::: "memory")
#define CPA_WAIT0()  asm volatile("cp.async.wait_group 0;" ::: "memory")

__device__ __forceinline__ void ldsm_x4(uint32_t a, uint32_t& r0, uint32_t& r1, uint32_t& r2, uint32_t& r3) {
    asm volatile("ldmatrix.sync.aligned.m8n8.x4.shared.b16 {%0,%1,%2,%3}, [%4];"
                 : "=r"(r0), "=r"(r1), "=r"(r2), "=r"(r3) : "r"(a));
}
__device__ __forceinline__ void mma_f16(float* c, const uint32_t* a, const uint32_t* b) {
    asm volatile("mma.sync.aligned.m16n8k16.row.col.f32.f16.f16.f32 "
                 "{%0,%1,%2,%3}, {%4,%5,%6,%7}, {%8,%9}, {%0,%1,%2,%3};"
                 : "+f"(c[0]), "+f"(c[1]), "+f"(c[2]), "+f"(c[3])
                 : "r"(a[0]), "r"(a[1]), "r"(a[2]), "r"(a[3]), "r"(b[0]), "r"(b[1]));
}

// ---------------- split-fp16 helpers ----------------
__device__ __forceinline__ void splitf16(const float4& v, uint2& hi, uint2& lo) {
    __half2 h01 = __floats2half2_rn(v.x, v.y);
    __half2 h23 = __floats2half2_rn(v.z, v.w);
    float2 f01 = __half22float2(h01), f23 = __half22float2(h23);
    __half2 l01 = __floats2half2_rn(v.x - f01.x, v.y - f01.y);
    __half2 l23 = __floats2half2_rn(v.z - f23.x, v.w - f23.y);
    hi.x = *(uint32_t*)&h01; hi.y = *(uint32_t*)&h23;
    lo.x = *(uint32_t*)&l01; lo.y = *(uint32_t*)&l23;
}

// ---------------- A conversion: fp32 [8192,2048] -> fp16 [8192,4096] = [hi|lo] ----------------
__global__ __launch_bounds__(256) void ttt_cvtA(const float* __restrict__ src)
{
    int t = blockIdx.x * 256 + threadIdx.x;
    float4 v = ((const float4*)src)[t];
    int r = t >> 9, c4 = t & 511;
    size_t base = (size_t)r * KP + (c4 << 2);
    uint2 hi, lo;
    splitf16(v, hi, lo);
    *(uint2*)(g_A_hf + base)        = hi;
    *(uint2*)(g_A_hf + base + 2048) = lo;
}

// ---------------- B conversion (3 sources + zero pad): hi plane only ----------------
__global__ __launch_bounds__(256) void ttt_cvtB(const float* __restrict__ w0,
                                                const float* __restrict__ w1,
                                                const float* __restrict__ w2)
{
    int row = blockIdx.x;
    int tid = threadIdx.x;
    const float* srcp = nullptr;
    if (row < 2048) srcp = w0 + (size_t)row * 2048;
    else if (row < 4096) srcp = w1 + (size_t)(row - 2048) * 2048;
    else if (row < 4128) srcp = w2 + (size_t)(row - 4096) * 2048;
    float4 v0 = make_float4(0, 0, 0, 0), v1 = v0;
    if (srcp) { v0 = ((const float4*)srcp)[tid]; v1 = ((const float4*)srcp)[tid + 256]; }
    uint2 hi, lo;
    splitf16(v0, hi, lo);
    *(uint2*)(g_B_hf + (size_t)row * 2048 + (tid << 2)) = hi;
    splitf16(v1, hi, lo);
    *(uint2*)(g_B_hf + (size_t)row * 2048 + ((tid + 256) << 2)) = hi;
}

// ---------------- fp16 mma.sync GEMM: 128x128, 256 thr, B-dedup, 2-stage x 48KB ----------------
#define GS_STAGE 49152
#define GKSTEPS 32
__global__ __launch_bounds__(256, 2) void ttt_hgemm(float* Cext, int fused)
{
    extern __shared__ char smem[];
    uint32_t sb = smem_u32(smem);
    const int tid = threadIdx.x;
    const int wid = tid >> 5, lane = tid & 31;
    const int m0 = blockIdx.y << 7;
    const int n0 = blockIdx.x << 7;
    const int mw = (wid >> 2) << 6;
    const int nw = (wid & 3) << 5;

    const __half* Ab = g_A_hf + (size_t)m0 * KP;
    const __half* Bb = g_B_hf + (size_t)n0 * 2048;

    float acc[4][4][4];
#pragma unroll
    for (int i = 0; i < 4; i++)
#pragma unroll
        for (int j = 0; j < 4; j++)
#pragma unroll
            for (int q = 0; q < 4; q++) acc[i][j][q] = 0.0f;

    auto load_stage = [&](int s, int kt) {
        uint32_t sAh = sb + s * GS_STAGE;
        uint32_t sAl = sAh + 16384;
        uint32_t sB  = sAh + 32768;
#pragma unroll
        for (int i = 0; i < 4; i++) {
            int idx = tid + (i << 8);
            int row = idx >> 3, c = idx & 7;
            uint32_t soff = (uint32_t)(row << 7) + (((uint32_t)(c ^ (row & 7))) << 4);
            const __half* ar = Ab + (size_t)row * KP + kt * 64 + c * 8;
            CPA16(sAh + soff, (const char*)ar);
            CPA16(sAl + soff, (const char*)(ar + 2048));
            CPA16(sB + soff, (const char*)(Bb + (size_t)row * 2048 + kt * 64 + c * 8));
        }
        CPA_COMMIT();
    };

    load_stage(0, 0);
    const int lr15 = lane & 15, lhi = lane >> 4;

    for (int kt = 0; kt < GKSTEPS; kt++) {
        int s = kt & 1;
        if (kt + 1 < GKSTEPS) {
            load_stage(s ^ 1, kt + 1);
            asm volatile("cp.async.wait_group 1;" ::: "memory");
        } else {
            CPA_WAIT0();
        }
        __syncthreads();

        uint32_t aH = sb + s * GS_STAGE;
        uint32_t aL = aH + 16384;
        uint32_t bB = aH + 32768;
#pragma unroll
        for (int ks = 0; ks < 4; ks++) {
            uint32_t bf[4][2];
#pragma unroll
            for (int np = 0; np < 2; np++) {
                int row = nw + np * 16 + lr15;
                uint32_t bd = bB + (uint32_t)(row << 7) + ((uint32_t)((2 * ks + lhi) ^ (row & 7)) << 4);
                uint32_t r0, r1, r2, r3;
                ldsm_x4(bd, r0, r1, r2, r3);
                bf[np * 2][0] = r0;     bf[np * 2][1] = r2;
                bf[np * 2 + 1][0] = r1; bf[np * 2 + 1][1] = r3;
            }
            uint32_t af[4][4];
#pragma unroll
            for (int mt = 0; mt < 4; mt++) {
                int row = mw + mt * 16 + lr15;
                uint32_t ad = aH + (uint32_t)(row << 7) + ((uint32_t)((2 * ks + lhi) ^ (row & 7)) << 4);
                ldsm_x4(ad, af[mt][0], af[mt][1], af[mt][2], af[mt][3]);
            }
#pragma unroll
            for (int mt = 0; mt < 4; mt++)
#pragma unroll
                for (int nt = 0; nt < 4; nt++)
                    mma_f16(acc[mt][nt], af[mt], bf[nt]);
#pragma unroll
            for (int mt = 0; mt < 4; mt++) {
                int row = mw + mt * 16 + lr15;
                uint32_t ad = aL + (uint32_t)(row << 7) + ((uint32_t)((2 * ks + lhi) ^ (row & 7)) << 4);
                ldsm_x4(ad, af[mt][0], af[mt][1], af[mt][2], af[mt][3]);
            }
#pragma unroll
            for (int mt = 0; mt < 4; mt++)
#pragma unroll
                for (int nt = 0; nt < 4; nt++)
                    mma_f16(acc[mt][nt], af[mt], bf[nt]);
        }
        __syncthreads();
    }

#pragma unroll
    for (int mt = 0; mt < 4; mt++) {
#pragma unroll
        for (int nt = 0; nt < 4; nt++) {
            int col = n0 + nw + nt * 8 + (lane & 3) * 2;
            int row = m0 + mw + mt * 16 + (lane >> 2);
            float2 va = make_float2(acc[mt][nt][0], acc[mt][nt][1]);
            float2 vb = make_float2(acc[mt][nt][2], acc[mt][nt][3]);
            if (!fused) {
                *(float2*)(Cext + (size_t)row * 2048 + col) = va;
                *(float2*)(Cext + (size_t)(row + 8) * 2048 + col) = vb;
            } else if (col < 2048) {
                *(float2*)(g_xq + (size_t)row * 2048 + col) = va;
                *(float2*)(g_xq + (size_t)(row + 8) * 2048 + col) = vb;
            } else if (col < 4096) {
                *(float2*)(g_xv + (size_t)row * 2048 + col - 2048) = va;
                *(float2*)(g_xv + (size_t)(row + 8) * 2048 + col - 2048) = vb;
            } else if (col < 4128) {
                *(float2*)(g_lrraw + (size_t)row * 32 + col - 4096) = va;
                *(float2*)(g_lrraw + (size_t)(row + 8) * 32 + col - 4096) = vb;
            }
        }
    }
}

// ---------------- TTT scan with fused conv/rope/lr + fast LN reductions ----------------
__global__ __launch_bounds__(256) void ttt_scan_kernel(
    const float* __restrict__ lt_idx,
    const float* __restrict__ lnw_g, const float* __restrict__ lnb_g,
    const float* __restrict__ W1g,   const float* __restrict__ b1g,
    const float* __restrict__ cqw,   const float* __restrict__ cqb,
    const float* __restrict__ ckw,   const float* __restrict__ ckb,
    const float* __restrict__ lrb)
{
    __shared__ float W1[64][64];
    __shared__ float sraw[2][19][68];
    __shared__ float sxv[2][16][68];
    __shared__ float sxq[16][68], sxk[16][68];
    __shared__ float grad[16][68], z[16][68];
    __shared__ float attn[16][16];
    __shared__ float wq_s[256], wk_s[256];
    __shared__ float bq_s[64], bk_s[64];
    __shared__ float b1[64], lnw[64], lnb[64];
    __shared__ float lrrawbuf[2][16], lr_sh[16], tok[16];

    int tid = threadIdx.x;
    int b = blockIdx.x >> 5, h = blockIdx.x & 31;
    const int ch0 = h * 64;

    for (int o = tid; o < 4096; o += 256)
        ((float*)W1)[o] = W1g[(size_t)h * 4096 + o];
    if (tid < 64) {
        b1[tid]  = b1g[h * 64 + tid];
        lnw[tid] = lnw_g[h * 64 + tid];
        lnb[tid] = lnb_g[h * 64 + tid];
        bq_s[tid] = cqb[ch0 + tid];
        bk_s[tid] = ckb[ch0 + tid];
    }
    wq_s[tid] = cqw[ch0 * 4 + tid];
    wk_s[tid] = ckw[ch0 * 4 + tid];
    if (tid < 16) tok[tid] = fmaxf(1.0f / (float)(tid + 1) + lt_idx[tid], 0.0f);
    for (int o = tid; o < 2 * 19 * 68; o += 256)
        ((float*)sraw)[o] = 0.0f;

    const int warp = tid >> 5, lane = tid & 31;
    const int ii = tid >> 4;
    const int d0 = (tid & 15) * 4;
    const size_t base = ((size_t)b * LZ) * WD + (size_t)ch0;
    const float lrb_h = lrb[h];

    float cs0, sn0, cs1, sn1;
    {
        int i0 = d0 >> 1;
        float inv0 = exp2f(-(float)i0 * (13.2877123795f / 32.0f));
        float inv1 = exp2f(-(float)(i0 + 1) * (13.2877123795f / 32.0f));
        sincosf((float)ii * inv0, &sn0, &cs0);
        sincosf((float)ii * inv1, &sn1, &cs1);
    }
    __syncthreads();

    const uint32_t a_raw = smem_u32(&sraw[0][0][0]);
    const uint32_t a_xv  = smem_u32(&sxv[0][0][0]);
    const uint32_t a_lrr = smem_u32(&lrrawbuf[0][0]);
    const uint32_t RAWB = 19 * 68 * 4;
    const uint32_t XVB  = 16 * 68 * 4;

    auto prefetch = [&](int s, int n) {
#pragma unroll
        for (int it = 0; it < 2; it++) {
            int idx = tid + (it << 8);
            if (idx < 304) {
                int row = idx >> 4, c = idx & 15;
                int g = n * MBSZ - 3 + row;
                if (g >= 0)
                    CPA16(a_raw + s * RAWB + (uint32_t)(row * 272 + c * 16),
                          (const char*)&g_xq[base + (size_t)g * WD + c * 4]);
            }
        }
        {
            int row = tid >> 4, c = tid & 15;
            CPA16(a_xv + s * XVB + (uint32_t)(row * 272 + c * 16),
                  (const char*)&g_xv[base + (size_t)(n * MBSZ + row) * WD + c * 4]);
        }
        if (tid < 16)
            CPA4(a_lrr + s * 64 + tid * 4,
                 (const char*)&g_lrraw[((size_t)b * LZ + n * MBSZ + tid) * 32 + h]);
        CPA_COMMIT();
    };

    prefetch(0, 0);

    for (int n = 0; n < NMBC; n++) {
        const int s = n & 1;
        CPA_WAIT0();
        __syncthreads();
        if (n + 1 < NMBC) prefetch(s ^ 1, n + 1);

        // conv + rope
        {
            float4 t0 = *(const float4*)&sraw[s][ii + 0][d0];
            float4 t1 = *(const float4*)&sraw[s][ii + 1][d0];
            float4 t2 = *(const float4*)&sraw[s][ii + 2][d0];
            float4 t3 = *(const float4*)&sraw[s][ii + 3][d0];
            const float* ta = (const float*)&t0;
            const float* tb = (const float*)&t1;
            const float* tc = (const float*)&t2;
            const float* td = (const float*)&t3;
            float qv[4], kv[4];
#pragma unroll
            for (int d = 0; d < 4; d++) {
                int ch = d0 + d;
                qv[d] = bq_s[ch] + ta[d] * wq_s[ch * 4] + tb[d] * wq_s[ch * 4 + 1]
                                 + tc[d] * wq_s[ch * 4 + 2] + td[d] * wq_s[ch * 4 + 3];
                kv[d] = bk_s[ch] + ta[d] * wk_s[ch * 4] + tb[d] * wk_s[ch * 4 + 1]
                                 + tc[d] * wk_s[ch * 4 + 2] + td[d] * wk_s[ch * 4 + 3];
            }
            float4 oq, ok;
            oq.x = qv[0] * cs0 - qv[1] * sn0;  oq.y = qv[1] * cs0 + qv[0] * sn0;
            oq.z = qv[2] * cs1 - qv[3] * sn1;  oq.w = qv[3] * cs1 + qv[2] * sn1;
            ok.x = kv[0] * cs0 - kv[1] * sn0;  ok.y = kv[1] * cs0 + kv[0] * sn0;
            ok.z = kv[2] * cs1 - kv[3] * sn1;  ok.w = kv[3] * cs1 + kv[2] * sn1;
            *(float4*)&sxq[ii][d0] = oq;
            *(float4*)&sxk[ii][d0] = ok;
        }
        if (tid < 16)
            lr_sh[tid] = (1.0f / 64.0f) / (1.0f + expf(-(lrrawbuf[s][tid] + lrb_h)));
        __syncthreads();

        // Z1 = xk @ W1 + b1
        {
            float4 acc = *(const float4*)&b1[d0];
#pragma unroll 8
            for (int e = 0; e < 64; e++) {
                float xe = sxk[ii][e];
                float4 w = *(const float4*)&W1[e][d0];
                acc.x += xe * w.x; acc.y += xe * w.y; acc.z += xe * w.z; acc.w += xe * w.w;
            }
            *(float4*)&z[ii][d0] = acc;
        }
        // attn (float4 dot)
        {
            int i = tid >> 4, j = tid & 15;
            const float4* qa = (const float4*)&sxq[i][0];
            const float4* ka = (const float4*)&sxk[j][0];
            float sa = 0.0f;
#pragma unroll
            for (int d4 = 0; d4 < 16; d4++) {
                float4 a = qa[d4], c = ka[d4];
                sa += a.x * c.x + a.y * c.y + a.z * c.z + a.w * c.w;
            }
            attn[i][j] = sa;
        }
        __syncthreads();

        // grad = ln_l2_bwd(Z1, xv-xk): both rows of the warp at once, fused sum+sumsq
        {
            int r0 = warp * 2, r1 = r0 + 1;
            float a0 = z[r0][lane], a1 = z[r0][lane + 32];
            float c0 = z[r1][lane], c1 = z[r1][lane + 32];
            float sA = a0 + a1,           sB = c0 + c1;
            float qA = a0 * a0 + a1 * a1, qB = c0 * c0 + c1 * c1;
#pragma unroll
            for (int o = 16; o; o >>= 1) {
                sA += __shfl_xor_sync(0xffffffffu, sA, o);
                sB += __shfl_xor_sync(0xffffffffu, sB, o);
                qA += __shfl_xor_sync(0xffffffffu, qA, o);
                qB += __shfl_xor_sync(0xffffffffu, qB, o);
            }
            float muA = sA * (1.0f / 64.0f), muB = sB * (1.0f / 64.0f);
            float rstdA = rsqrtf(fmaxf(qA * (1.0f / 64.0f) - muA * muA, 0.0f) + EPSC);
            float rstdB = rsqrtf(fmaxf(qB * (1.0f / 64.0f) - muB * muB, 0.0f) + EPSC);
            float xhA0 = (a0 - muA) * rstdA, xhA1 = (a1 - muA) * rstdA;
            float xhB0 = (c0 - muB) * rstdB, xhB1 = (c1 - muB) * rstdB;
            float w0 = lnw[lane], w1 = lnw[lane + 32];
            float bb0 = lnb[lane], bb1 = lnb[lane + 32];
            float tA0 = sxv[s][r0][lane] - sxk[r0][lane];
            float tA1 = sxv[s][r0][lane + 32] - sxk[r0][lane + 32];
            float tB0 = sxv[s][r1][lane] - sxk[r1][lane];
            float tB1 = sxv[s][r1][lane + 32] - sxk[r1][lane + 32];
            float gyA0 = (w0 * xhA0 + bb0 - tA0) * w0;
            float gyA1 = (w1 * xhA1 + bb1 - tA1) * w1;
            float gyB0 = (w0 * xhB0 + bb0 - tB0) * w0;
            float gyB1 = (w1 * xhB1 + bb1 - tB1) * w1;
            float u1A = gyA0 + gyA1, u2A = gyA0 * xhA0 + gyA1 * xhA1;
            float u1B = gyB0 + gyB1, u2B = gyB0 * xhB0 + gyB1 * xhB1;
#pragma unroll
            for (int o = 16; o; o >>= 1) {
                u1A += __shfl_xor_sync(0xffffffffu, u1A, o);
                u2A += __shfl_xor_sync(0xffffffffu, u2A, o);
                u1B += __shfl_xor_sync(0xffffffffu, u1B, o);
                u2B += __shfl_xor_sync(0xffffffffu, u2B, o);
            }
            float scA = rstdA * (1.0f / 64.0f), scB = rstdB * (1.0f / 64.0f);
            grad[r0][lane]      = (64.0f * gyA0 - u1A - xhA0 * u2A) * scA;
            grad[r0][lane + 32] = (64.0f * gyA1 - u1A - xhA1 * u2A) * scA;
            grad[r1][lane]      = (64.0f * gyB0 - u1B - xhB0 * u2B) * scB;
            grad[r1][lane + 32] = (64.0f * gyB1 - u1B - xhB1 * u2B) * scB;
        }
        __syncthreads();

        // Z1_bar
        {
            float4 acc = *(const float4*)&b1[d0];
#pragma unroll 8
            for (int e = 0; e < 64; e++) {
                float xe = sxq[ii][e];
                float4 w = *(const float4*)&W1[e][d0];
                acc.x += xe * w.x; acc.y += xe * w.y; acc.z += xe * w.z; acc.w += xe * w.w;
            }
            float tk = tok[ii];
            for (int j = 0; j <= ii; j++) {
                float cf = tk * lr_sh[j] * (attn[ii][j] + 1.0f);
                float4 gr = *(const float4*)&grad[j][d0];
                acc.x -= cf * gr.x; acc.y -= cf * gr.y; acc.z -= cf * gr.z; acc.w -= cf * gr.w;
            }
            *(float4*)&z[ii][d0] = acc;
        }
        __syncthreads();

        // out = xq + ln_fwd(Z1_bar): both rows at once, fused sum+sumsq
        {
            int r0 = warp * 2, r1 = r0 + 1;
            float a0 = z[r0][lane], a1 = z[r0][lane + 32];
            float c0 = z[r1][lane], c1 = z[r1][lane + 32];
            float sA = a0 + a1,           sB = c0 + c1;
            float qA = a0 * a0 + a1 * a1, qB = c0 * c0 + c1 * c1;
#pragma unroll
            for (int o = 16; o; o >>= 1) {
                sA += __shfl_xor_sync(0xffffffffu, sA, o);
                sB += __shfl_xor_sync(0xffffffffu, sB, o);
                qA += __shfl_xor_sync(0xffffffffu, qA, o);
                qB += __shfl_xor_sync(0xffffffffu, qB, o);
            }
            float muA = sA * (1.0f / 64.0f), muB = sB * (1.0f / 64.0f);
            float rstdA = rsqrtf(fmaxf(qA * (1.0f / 64.0f) - muA * muA, 0.0f) + EPSC);
            float rstdB = rsqrtf(fmaxf(qB * (1.0f / 64.0f) - muB * muB, 0.0f) + EPSC);
            float w0 = lnw[lane], w1 = lnw[lane + 32];
            float bb0 = lnb[lane], bb1 = lnb[lane + 32];
            size_t go0 = base + (size_t)(n * MBSZ + r0) * WD;
            size_t go1 = base + (size_t)(n * MBSZ + r1) * WD;
            g_scan[go0 + lane]      = sxq[r0][lane]      + w0 * ((a0 - muA) * rstdA) + bb0;
            g_scan[go0 + lane + 32] = sxq[r0][lane + 32] + w1 * ((a1 - muA) * rstdA) + bb1;
            g_scan[go1 + lane]      = sxq[r1][lane]      + w0 * ((c0 - muB) * rstdB) + bb0;
            g_scan[go1 + lane + 32] = sxq[r1][lane + 32] + w1 * ((c1 - muB) * rstdB) + bb1;
        }

        // W1/b1 state update
        {
            float te = tok[15];
#pragma unroll
            for (int p = 0; p < 4; p++) {
                int d = ii * 4 + p;
                float4 acc = *(const float4*)&W1[d][d0];
#pragma unroll
                for (int j = 0; j < 16; j++) {
                    float cf = te * lr_sh[j] * sxk[j][d];
                    float4 gr = *(const float4*)&grad[j][d0];
                    acc.x -= cf * gr.x; acc.y -= cf * gr.y; acc.z -= cf * gr.z; acc.w -= cf * gr.w;
                }
                *(float4*)&W1[d][d0] = acc;
            }
            if (tid < 64) {
                float sm = 0.0f;
#pragma unroll
                for (int j = 0; j < 16; j++) sm += lr_sh[j] * grad[j][tid];
                b1[tid] -= te * sm;
            }
        }
        __syncthreads();
    }
}

// ---------------- post layer-norm fused with A split-fp16 conversion ----------------
__global__ __launch_bounds__(256) void ttt_postnorm_cvt(
    const float* __restrict__ pw, const float* __restrict__ pb)
{
    __shared__ float red[8];
    int bl = blockIdx.x, tid = threadIdx.x;
    int lane = tid & 31, warp = tid >> 5;
    const float4* src = (const float4*)(g_scan + (size_t)bl * WD);
    float4 v0 = src[tid], v1 = src[tid + 256];

    float s = v0.x + v0.y + v0.z + v0.w + v1.x + v1.y + v1.z + v1.w;
#pragma unroll
    for (int o = 16; o; o >>= 1) s += __shfl_xor_sync(0xffffffffu, s, o);
    if (lane == 0) red[warp] = s;
    __syncthreads();
    float tot = 0.0f;
#pragma unroll
    for (int i = 0; i < 8; i++) tot += red[i];
    float mu = tot * (1.0f / 2048.0f);
    __syncthreads();

    float q =
        (v0.x - mu) * (v0.x - mu) + (v0.y - mu) * (v0.y - mu) +
        (v0.z - mu) * (v0.z - mu) + (v0.w - mu) * (v0.w - mu) +
        (v1.x - mu) * (v1.x - mu) + (v1.y - mu) * (v1.y - mu) +
        (v1.z - mu) * (v1.z - mu) + (v1.w - mu) * (v1.w - mu);
#pragma unroll
    for (int o = 16; o; o >>= 1) q += __shfl_xor_sync(0xffffffffu, q, o);
    if (lane == 0) red[warp] = q;
    __syncthreads();
    float qt = 0.0f;
#pragma unroll
    for (int i = 0; i < 8; i++) qt += red[i];
    float rstd = rsqrtf(qt * (1.0f / 2048.0f) + EPSC);

    float4 w0 = ((const float4*)pw)[tid], w1 = ((const float4*)pw)[tid + 256];
    float4 b0 = ((const float4*)pb)[tid], b1v = ((const float4*)pb)[tid + 256];
    float4 o0, o1;
    o0.x = (v0.x - mu) * rstd * w0.x + b0.x;
    o0.y = (v0.y - mu) * rstd * w0.y + b0.y;
    o0.z = (v0.z - mu) * rstd * w0.z + b0.z;
    o0.w = (v0.w - mu) * rstd * w0.w + b0.w;
    o1.x = (v1.x - mu) * rstd * w1.x + b1v.x;
    o1.y = (v1.y - mu) * rstd * w1.y + b1v.y;
    o1.z = (v1.z - mu) * rstd * w1.z + b1v.z;
    o1.w = (v1.w - mu) * rstd * w1.w + b1v.w;

    size_t base0 = (size_t)bl * KP + (tid << 2);
    size_t base1 = (size_t)bl * KP + ((tid + 256) << 2);
    uint2 hi, lo;
    splitf16(o0, hi, lo);
    *(uint2*)(g_A_hf + base0)        = hi;
    *(uint2*)(g_A_hf + base0 + 2048) = lo;
    splitf16(o1, hi, lo);
    *(uint2*)(g_A_hf + base1)        = hi;
    *(uint2*)(g_A_hf + base1 + 2048) = lo;
}

// ---------------- launcher ----------------
extern "C" void kernel_launch(void* const* d_in, const int* in_sizes, int n_in,
                              void* d_out, int out_size)
{
    const float* hs  = (const float*)d_in[0];
    const float* q_w = (const float*)d_in[1];
    const float* v_w = (const float*)d_in[2];
    const float* o_w = (const float*)d_in[3];
    const float* cqw = (const float*)d_in[4];
    const float* cqb = (const float*)d_in[5];
    const float* ckw = (const float*)d_in[6];
    const float* ckb = (const float*)d_in[7];
    const float* lrw = (const float*)d_in[8];
    const float* lrb = (const float*)d_in[9];
    const float* lti = (const float*)d_in[10];
    const float* tnw = (const float*)d_in[11];
    const float* tnb = (const float*)d_in[12];
    const float* W1i = (const float*)d_in[13];
    const float* b1i = (const float*)d_in[14];
    const float* pnw = (const float*)d_in[15];
    const float* pnb = (const float*)d_in[16];
    float* out = (float*)d_out;

    static int smem_set = 0;
    if (!smem_set) {
        cudaFuncSetAttribute(ttt_hgemm, cudaFuncAttributeMaxDynamicSharedMemorySize, 2 * GS_STAGE);
        smem_set = 1;
    }

    // fused QV+lr projection: A=hs, B=[q_w; v_w; lr_w; pad]
    ttt_cvtA<<<16384, 256>>>(hs);
    ttt_cvtB<<<NROWS_B, 256>>>(q_w, v_w, lrw);
    ttt_hgemm<<<dim3(33, 64), 256, 2 * GS_STAGE>>>(nullptr, 1);   // -> g_xq, g_xv, g_lrraw

    // scan (conv+rope+lr fused inside)
    ttt_scan_kernel<<<BZ * NHD, 256>>>(lti, tnw, tnb, W1i, b1i, cqw, cqb, ckw, ckb, lrb);

    // B for final GEMM (stream-ordered after GEMM1 read g_B_hf)
    ttt_cvtB<<<2048, 256>>>(o_w, o_w, o_w);
    ttt_postnorm_cvt<<<BZ * LZ, 256>>>(pnw, pnb);                 // -> g_A_hf

    ttt_hgemm<<<dim3(16, 64), 256, 2 * GS_STAGE>>>(out, 0);
}

// round 14
// speedup vs baseline: 1.0443x; 1.0212x over previous
#include <cuda_runtime.h>
#include <cuda_fp16.h>
#include <math.h>
#include <stdint.h>

#define BZ 4
#define LZ 2048
#define WD 2048
#define NHD 32
#define HDM 64
#define MBSZ 16
#define NMBC 128
#define EPSC 1e-6f
#define ELEMS (BZ*LZ*WD)
#define KP 4096            // split-fp16 A: [hi | lo]
#define NROWS_B 4224       // 2048 q + 2048 v + 32 lr + 96 pad (33*128)

// ---------------- scratch (device globals; no allocation) ----------------
__device__ float g_xq[ELEMS];
__device__ float g_xv[ELEMS];
__device__ float g_scan[ELEMS];
__device__ float g_lrraw[8192 * 32];
__device__ __half g_A_hf[(size_t)8192 * KP];       // [hi | lo]
__device__ __half g_B_hf[(size_t)NROWS_B * 2048];  // hi plane only (dedup)

// ---------------- PTX helpers ----------------
__device__ __forceinline__ uint32_t smem_u32(const void* p) {
    uint32_t a;
    asm("{ .reg .u64 t; cvta.to.shared.u64 t, %1; cvt.u32.u64 %0, t; }" : "=r"(a) : "l"(p));
    return a;
}
#define CPA16(d, s) asm volatile("cp.async.cg.shared.global [%0], [%1], 16;" :: "r"(d), "l"(s) : "memory")
#define CPA4(d, s)  asm volatile("cp.async.ca.shared.global [%0], [%1], 4;"  :: "r"(d), "l"(s) : "memory")
#define CPA_COMMIT() asm volatile("cp.async.commit_group;" ::: "memory")
#define CPA_WAIT0()  asm volatile("cp.async.wait_group 0;" ::: "memory")

__device__ __forceinline__ void ldsm_x4(uint32_t a, uint32_t& r0, uint32_t& r1, uint32_t& r2, uint32_t& r3) {
    asm volatile("ldmatrix.sync.aligned.m8n8.x4.shared.b16 {%0,%1,%2,%3}, [%4];"
                 : "=r"(r0), "=r"(r1), "=r"(r2), "=r"(r3) : "r"(a));
}
__device__ __forceinline__ void mma_f16(float* c, const uint32_t* a, const uint32_t* b) {
    asm volatile("mma.sync.aligned.m16n8k16.row.col.f32.f16.f16.f32 "
                 "{%0,%1,%2,%3}, {%4,%5,%6,%7}, {%8,%9}, {%0,%1,%2,%3};"
                 : "+f"(c[0]), "+f"(c[1]), "+f"(c[2]), "+f"(c[3])
                 : "r"(a[0]), "r"(a[1]), "r"(a[2]), "r"(a[3]), "r"(b[0]), "r"(b[1]));
}

// ---------------- split-fp16 helpers ----------------
__device__ __forceinline__ void splitf16(const float4& v, uint2& hi, uint2& lo) {
    __half2 h01 = __floats2half2_rn(v.x, v.y);
    __half2 h23 = __floats2half2_rn(v.z, v.w);
    float2 f01 = __half22float2(h01), f23 = __half22float2(h23);
    __half2 l01 = __floats2half2_rn(v.x - f01.x, v.y - f01.y);
    __half2 l23 = __floats2half2_rn(v.z - f23.x, v.w - f23.y);
    hi.x = *(uint32_t*)&h01; hi.y = *(uint32_t*)&h23;
    lo.x = *(uint32_t*)&l01; lo.y = *(uint32_t*)&l23;
}

// ---------------- A conversion: fp32 [8192,2048] -> fp16 [8192,4096] = [hi|lo] ----------------
__global__ __launch_bounds__(256) void ttt_cvtA(const float* __restrict__ src)
{
    int t = blockIdx.x * 256 + threadIdx.x;
    float4 v = ((const float4*)src)[t];
    int r = t >> 9, c4 = t & 511;
    size_t base = (size_t)r * KP + (c4 << 2);
    uint2 hi, lo;
    splitf16(v, hi, lo);
    *(uint2*)(g_A_hf + base)        = hi;
    *(uint2*)(g_A_hf + base + 2048) = lo;
}

// ---------------- B conversion (3 sources + zero pad): hi plane only ----------------
__global__ __launch_bounds__(256) void ttt_cvtB(const float* __restrict__ w0,
                                                const float* __restrict__ w1,
                                                const float* __restrict__ w2)
{
    int row = blockIdx.x;
    int tid = threadIdx.x;
    const float* srcp = nullptr;
    if (row < 2048) srcp = w0 + (size_t)row * 2048;
    else if (row < 4096) srcp = w1 + (size_t)(row - 2048) * 2048;
    else if (row < 4128) srcp = w2 + (size_t)(row - 4096) * 2048;
    float4 v0 = make_float4(0, 0, 0, 0), v1 = v0;
    if (srcp) { v0 = ((const float4*)srcp)[tid]; v1 = ((const float4*)srcp)[tid + 256]; }
    uint2 hi, lo;
    splitf16(v0, hi, lo);
    *(uint2*)(g_B_hf + (size_t)row * 2048 + (tid << 2)) = hi;
    splitf16(v1, hi, lo);
    *(uint2*)(g_B_hf + (size_t)row * 2048 + ((tid + 256) << 2)) = hi;
}

// ---------------- fp16 mma.sync GEMM: 128x128, 256 thr, B-dedup, 2-stage x 48KB ----------------
#define GS_STAGE 49152
#define GKSTEPS 32
__global__ __launch_bounds__(256, 2) void ttt_hgemm(float* Cext, int fused)
{
    extern __shared__ char smem[];
    uint32_t sb = smem_u32(smem);
    const int tid = threadIdx.x;
    const int wid = tid >> 5, lane = tid & 31;
    const int m0 = blockIdx.y << 7;
    const int n0 = blockIdx.x << 7;
    const int mw = (wid >> 2) << 6;
    const int nw = (wid & 3) << 5;

    const __half* Ab = g_A_hf + (size_t)m0 * KP;
    const __half* Bb = g_B_hf + (size_t)n0 * 2048;

    float acc[4][4][4];
#pragma unroll
    for (int i = 0; i < 4; i++)
#pragma unroll
        for (int j = 0; j < 4; j++)
#pragma unroll
            for (int q = 0; q < 4; q++) acc[i][j][q] = 0.0f;

    auto load_stage = [&](int s, int kt) {
        uint32_t sAh = sb + s * GS_STAGE;
        uint32_t sAl = sAh + 16384;
        uint32_t sB  = sAh + 32768;
#pragma unroll
        for (int i = 0; i < 4; i++) {
            int idx = tid + (i << 8);
            int row = idx >> 3, c = idx & 7;
            uint32_t soff = (uint32_t)(row << 7) + (((uint32_t)(c ^ (row & 7))) << 4);
            const __half* ar = Ab + (size_t)row * KP + kt * 64 + c * 8;
            CPA16(sAh + soff, (const char*)ar);
            CPA16(sAl + soff, (const char*)(ar + 2048));
            CPA16(sB + soff, (const char*)(Bb + (size_t)row * 2048 + kt * 64 + c * 8));
        }
        CPA_COMMIT();
    };

    load_stage(0, 0);
    const int lr15 = lane & 15, lhi = lane >> 4;

    for (int kt = 0; kt < GKSTEPS; kt++) {
        int s = kt & 1;
        if (kt + 1 < GKSTEPS) {
            load_stage(s ^ 1, kt + 1);
            asm volatile("cp.async.wait_group 1;" ::: "memory");
        } else {
            CPA_WAIT0();
        }
        __syncthreads();

        uint32_t aH = sb + s * GS_STAGE;
        uint32_t aL = aH + 16384;
        uint32_t bB = aH + 32768;
#pragma unroll
        for (int ks = 0; ks < 4; ks++) {
            uint32_t bf[4][2];
#pragma unroll
            for (int np = 0; np < 2; np++) {
                int row = nw + np * 16 + lr15;
                uint32_t bd = bB + (uint32_t)(row << 7) + ((uint32_t)((2 * ks + lhi) ^ (row & 7)) << 4);
                uint32_t r0, r1, r2, r3;
                ldsm_x4(bd, r0, r1, r2, r3);
                bf[np * 2][0] = r0;     bf[np * 2][1] = r2;
                bf[np * 2 + 1][0] = r1; bf[np * 2 + 1][1] = r3;
            }
            uint32_t af[4][4];
#pragma unroll
            for (int mt = 0; mt < 4; mt++) {
                int row = mw + mt * 16 + lr15;
                uint32_t ad = aH + (uint32_t)(row << 7) + ((uint32_t)((2 * ks + lhi) ^ (row & 7)) << 4);
                ldsm_x4(ad, af[mt][0], af[mt][1], af[mt][2], af[mt][3]);
            }
#pragma unroll
            for (int mt = 0; mt < 4; mt++)
#pragma unroll
                for (int nt = 0; nt < 4; nt++)
                    mma_f16(acc[mt][nt], af[mt], bf[nt]);
#pragma unroll
            for (int mt = 0; mt < 4; mt++) {
                int row = mw + mt * 16 + lr15;
                uint32_t ad = aL + (uint32_t)(row << 7) + ((uint32_t)((2 * ks + lhi) ^ (row & 7)) << 4);
                ldsm_x4(ad, af[mt][0], af[mt][1], af[mt][2], af[mt][3]);
            }
#pragma unroll
            for (int mt = 0; mt < 4; mt++)
#pragma unroll
                for (int nt = 0; nt < 4; nt++)
                    mma_f16(acc[mt][nt], af[mt], bf[nt]);
        }
        __syncthreads();
    }

#pragma unroll
    for (int mt = 0; mt < 4; mt++) {
#pragma unroll
        for (int nt = 0; nt < 4; nt++) {
            int col = n0 + nw + nt * 8 + (lane & 3) * 2;
            int row = m0 + mw + mt * 16 + (lane >> 2);
            float2 va = make_float2(acc[mt][nt][0], acc[mt][nt][1]);
            float2 vb = make_float2(acc[mt][nt][2], acc[mt][nt][3]);
            if (!fused) {
                *(float2*)(Cext + (size_t)row * 2048 + col) = va;
                *(float2*)(Cext + (size_t)(row + 8) * 2048 + col) = vb;
            } else if (col < 2048) {
                *(float2*)(g_xq + (size_t)row * 2048 + col) = va;
                *(float2*)(g_xq + (size_t)(row + 8) * 2048 + col) = vb;
            } else if (col < 4096) {
                *(float2*)(g_xv + (size_t)row * 2048 + col - 2048) = va;
                *(float2*)(g_xv + (size_t)(row + 8) * 2048 + col - 2048) = vb;
            } else if (col < 4128) {
                *(float2*)(g_lrraw + (size_t)row * 32 + col - 4096) = va;
                *(float2*)(g_lrraw + (size_t)(row + 8) * 32 + col - 4096) = vb;
            }
        }
    }
}

// ---------------- TTT scan: fused conv/rope/lr, float4 matmuls, low-LDS update ----------------
__global__ __launch_bounds__(256) void ttt_scan_kernel(
    const float* __restrict__ lt_idx,
    const float* __restrict__ lnw_g, const float* __restrict__ lnb_g,
    const float* __restrict__ W1g,   const float* __restrict__ b1g,
    const float* __restrict__ cqw,   const float* __restrict__ cqb,
    const float* __restrict__ ckw,   const float* __restrict__ ckb,
    const float* __restrict__ lrb)
{
    __shared__ float W1[64][64];
    __shared__ float sraw[2][19][68];
    __shared__ float sxv[2][16][68];
    __shared__ float sxq[16][68], sxk[16][68];
    __shared__ float grad[16][68], z[16][68];
    __shared__ float attn[16][16];
    __shared__ float wq_s[256], wk_s[256];
    __shared__ float bq_s[64], bk_s[64];
    __shared__ float b1[64], lnw[64], lnb[64];
    __shared__ float lrrawbuf[2][16], lr_sh[16], tok[16];

    int tid = threadIdx.x;
    int b = blockIdx.x >> 5, h = blockIdx.x & 31;
    const int ch0 = h * 64;

    for (int o = tid; o < 4096; o += 256)
        ((float*)W1)[o] = W1g[(size_t)h * 4096 + o];
    if (tid < 64) {
        b1[tid]  = b1g[h * 64 + tid];
        lnw[tid] = lnw_g[h * 64 + tid];
        lnb[tid] = lnb_g[h * 64 + tid];
        bq_s[tid] = cqb[ch0 + tid];
        bk_s[tid] = ckb[ch0 + tid];
    }
    wq_s[tid] = cqw[ch0 * 4 + tid];
    wk_s[tid] = ckw[ch0 * 4 + tid];
    if (tid < 16) tok[tid] = fmaxf(1.0f / (float)(tid + 1) + lt_idx[tid], 0.0f);
    for (int o = tid; o < 2 * 19 * 68; o += 256)
        ((float*)sraw)[o] = 0.0f;

    const int warp = tid >> 5, lane = tid & 31;
    const int ii = tid >> 4;
    const int d0 = (tid & 15) * 4;
    const size_t base = ((size_t)b * LZ) * WD + (size_t)ch0;
    const float lrb_h = lrb[h];

    float cs0, sn0, cs1, sn1;
    {
        int i0 = d0 >> 1;
        float inv0 = exp2f(-(float)i0 * (13.2877123795f / 32.0f));
        float inv1 = exp2f(-(float)(i0 + 1) * (13.2877123795f / 32.0f));
        sincosf((float)ii * inv0, &sn0, &cs0);
        sincosf((float)ii * inv1, &sn1, &cs1);
    }
    __syncthreads();

    const uint32_t a_raw = smem_u32(&sraw[0][0][0]);
    const uint32_t a_xv  = smem_u32(&sxv[0][0][0]);
    const uint32_t a_lrr = smem_u32(&lrrawbuf[0][0]);
    const uint32_t RAWB = 19 * 68 * 4;
    const uint32_t XVB  = 16 * 68 * 4;

    auto prefetch = [&](int s, int n) {
#pragma unroll
        for (int it = 0; it < 2; it++) {
            int idx = tid + (it << 8);
            if (idx < 304) {
                int row = idx >> 4, c = idx & 15;
                int g = n * MBSZ - 3 + row;
                if (g >= 0)
                    CPA16(a_raw + s * RAWB + (uint32_t)(row * 272 + c * 16),
                          (const char*)&g_xq[base + (size_t)g * WD + c * 4]);
            }
        }
        {
            int row = tid >> 4, c = tid & 15;
            CPA16(a_xv + s * XVB + (uint32_t)(row * 272 + c * 16),
                  (const char*)&g_xv[base + (size_t)(n * MBSZ + row) * WD + c * 4]);
        }
        if (tid < 16)
            CPA4(a_lrr + s * 64 + tid * 4,
                 (const char*)&g_lrraw[((size_t)b * LZ + n * MBSZ + tid) * 32 + h]);
        CPA_COMMIT();
    };

    prefetch(0, 0);

    for (int n = 0; n < NMBC; n++) {
        const int s = n & 1;
        CPA_WAIT0();
        __syncthreads();
        if (n + 1 < NMBC) prefetch(s ^ 1, n + 1);

        // conv + rope
        {
            float4 t0 = *(const float4*)&sraw[s][ii + 0][d0];
            float4 t1 = *(const float4*)&sraw[s][ii + 1][d0];
            float4 t2 = *(const float4*)&sraw[s][ii + 2][d0];
            float4 t3 = *(const float4*)&sraw[s][ii + 3][d0];
            const float* ta = (const float*)&t0;
            const float* tb = (const float*)&t1;
            const float* tc = (const float*)&t2;
            const float* td = (const float*)&t3;
            float qv[4], kv[4];
#pragma unroll
            for (int d = 0; d < 4; d++) {
                int ch = d0 + d;
                qv[d] = bq_s[ch] + ta[d] * wq_s[ch * 4] + tb[d] * wq_s[ch * 4 + 1]
                                 + tc[d] * wq_s[ch * 4 + 2] + td[d] * wq_s[ch * 4 + 3];
                kv[d] = bk_s[ch] + ta[d] * wk_s[ch * 4] + tb[d] * wk_s[ch * 4 + 1]
                                 + tc[d] * wk_s[ch * 4 + 2] + td[d] * wk_s[ch * 4 + 3];
            }
            float4 oq, ok;
            oq.x = qv[0] * cs0 - qv[1] * sn0;  oq.y = qv[1] * cs0 + qv[0] * sn0;
            oq.z = qv[2] * cs1 - qv[3] * sn1;  oq.w = qv[3] * cs1 + qv[2] * sn1;
            ok.x = kv[0] * cs0 - kv[1] * sn0;  ok.y = kv[1] * cs0 + kv[0] * sn0;
            ok.z = kv[2] * cs1 - kv[3] * sn1;  ok.w = kv[3] * cs1 + kv[2] * sn1;
            *(float4*)&sxq[ii][d0] = oq;
            *(float4*)&sxk[ii][d0] = ok;
        }
        if (tid < 16)
            lr_sh[tid] = (1.0f / 64.0f) / (1.0f + expf(-(lrrawbuf[s][tid] + lrb_h)));
        __syncthreads();

        // Z1 = xk @ W1 + b1 (float4 x-loads)
        {
            float4 acc = *(const float4*)&b1[d0];
#pragma unroll
            for (int e4 = 0; e4 < 16; e4++) {
                float4 xv4 = *(const float4*)&sxk[ii][e4 * 4];
                float4 w;
                w = *(const float4*)&W1[e4 * 4 + 0][d0];
                acc.x += xv4.x * w.x; acc.y += xv4.x * w.y; acc.z += xv4.x * w.z; acc.w += xv4.x * w.w;
                w = *(const float4*)&W1[e4 * 4 + 1][d0];
                acc.x += xv4.y * w.x; acc.y += xv4.y * w.y; acc.z += xv4.y * w.z; acc.w += xv4.y * w.w;
                w = *(const float4*)&W1[e4 * 4 + 2][d0];
                acc.x += xv4.z * w.x; acc.y += xv4.z * w.y; acc.z += xv4.z * w.z; acc.w += xv4.z * w.w;
                w = *(const float4*)&W1[e4 * 4 + 3][d0];
                acc.x += xv4.w * w.x; acc.y += xv4.w * w.y; acc.z += xv4.w * w.z; acc.w += xv4.w * w.w;
            }
            *(float4*)&z[ii][d0] = acc;
        }
        // attn (float4 dot)
        {
            int i = tid >> 4, j = tid & 15;
            const float4* qa = (const float4*)&sxq[i][0];
            const float4* ka = (const float4*)&sxk[j][0];
            float sa = 0.0f;
#pragma unroll
            for (int d4 = 0; d4 < 16; d4++) {
                float4 a = qa[d4], c = ka[d4];
                sa += a.x * c.x + a.y * c.y + a.z * c.z + a.w * c.w;
            }
            attn[i][j] = sa;
        }
        __syncthreads();

        // grad = ln_l2_bwd(Z1, xv-xk): both rows at once, fused sum+sumsq
        {
            int r0 = warp * 2, r1 = r0 + 1;
            float a0 = z[r0][lane], a1 = z[r0][lane + 32];
            float c0 = z[r1][lane], c1 = z[r1][lane + 32];
            float sA = a0 + a1,           sB = c0 + c1;
            float qA = a0 * a0 + a1 * a1, qB = c0 * c0 + c1 * c1;
#pragma unroll
            for (int o = 16; o; o >>= 1) {
                sA += __shfl_xor_sync(0xffffffffu, sA, o);
                sB += __shfl_xor_sync(0xffffffffu, sB, o);
                qA += __shfl_xor_sync(0xffffffffu, qA, o);
                qB += __shfl_xor_sync(0xffffffffu, qB, o);
            }
            float muA = sA * (1.0f / 64.0f), muB = sB * (1.0f / 64.0f);
            float rstdA = rsqrtf(fmaxf(qA * (1.0f / 64.0f) - muA * muA, 0.0f) + EPSC);
            float rstdB = rsqrtf(fmaxf(qB * (1.0f / 64.0f) - muB * muB, 0.0f) + EPSC);
            float xhA0 = (a0 - muA) * rstdA, xhA1 = (a1 - muA) * rstdA;
            float xhB0 = (c0 - muB) * rstdB, xhB1 = (c1 - muB) * rstdB;
            float w0 = lnw[lane], w1 = lnw[lane + 32];
            float bb0 = lnb[lane], bb1 = lnb[lane + 32];
            float tA0 = sxv[s][r0][lane] - sxk[r0][lane];
            float tA1 = sxv[s][r0][lane + 32] - sxk[r0][lane + 32];
            float tB0 = sxv[s][r1][lane] - sxk[r1][lane];
            float tB1 = sxv[s][r1][lane + 32] - sxk[r1][lane + 32];
            float gyA0 = (w0 * xhA0 + bb0 - tA0) * w0;
            float gyA1 = (w1 * xhA1 + bb1 - tA1) * w1;
            float gyB0 = (w0 * xhB0 + bb0 - tB0) * w0;
            float gyB1 = (w1 * xhB1 + bb1 - tB1) * w1;
            float u1A = gyA0 + gyA1, u2A = gyA0 * xhA0 + gyA1 * xhA1;
            float u1B = gyB0 + gyB1, u2B = gyB0 * xhB0 + gyB1 * xhB1;
#pragma unroll
            for (int o = 16; o; o >>= 1) {
                u1A += __shfl_xor_sync(0xffffffffu, u1A, o);
                u2A += __shfl_xor_sync(0xffffffffu, u2A, o);
                u1B += __shfl_xor_sync(0xffffffffu, u1B, o);
                u2B += __shfl_xor_sync(0xffffffffu, u2B, o);
            }
            float scA = rstdA * (1.0f / 64.0f), scB = rstdB * (1.0f / 64.0f);
            grad[r0][lane]      = (64.0f * gyA0 - u1A - xhA0 * u2A) * scA;
            grad[r0][lane + 32] = (64.0f * gyA1 - u1A - xhA1 * u2A) * scA;
            grad[r1][lane]      = (64.0f * gyB0 - u1B - xhB0 * u2B) * scB;
            grad[r1][lane + 32] = (64.0f * gyB1 - u1B - xhB1 * u2B) * scB;
        }
        __syncthreads();

        // Z1_bar (float4 x-loads)
        {
            float4 acc = *(const float4*)&b1[d0];
#pragma unroll
            for (int e4 = 0; e4 < 16; e4++) {
                float4 xv4 = *(const float4*)&sxq[ii][e4 * 4];
                float4 w;
                w = *(const float4*)&W1[e4 * 4 + 0][d0];
                acc.x += xv4.x * w.x; acc.y += xv4.x * w.y; acc.z += xv4.x * w.z; acc.w += xv4.x * w.w;
                w = *(const float4*)&W1[e4 * 4 + 1][d0];
                acc.x += xv4.y * w.x; acc.y += xv4.y * w.y; acc.z += xv4.y * w.z; acc.w += xv4.y * w.w;
                w = *(const float4*)&W1[e4 * 4 + 2][d0];
                acc.x += xv4.z * w.x; acc.y += xv4.z * w.y; acc.z += xv4.z * w.z; acc.w += xv4.z * w.w;
                w = *(const float4*)&W1[e4 * 4 + 3][d0];
                acc.x += xv4.w * w.x; acc.y += xv4.w * w.y; acc.z += xv4.w * w.z; acc.w += xv4.w * w.w;
            }
            float tk = tok[ii];
            for (int j = 0; j <= ii; j++) {
                float cf = tk * lr_sh[j] * (attn[ii][j] + 1.0f);
                float4 gr = *(const float4*)&grad[j][d0];
                acc.x -= cf * gr.x; acc.y -= cf * gr.y; acc.z -= cf * gr.z; acc.w -= cf * gr.w;
            }
            *(float4*)&z[ii][d0] = acc;
        }
        __syncthreads();

        // out = xq + ln_fwd(Z1_bar): both rows at once
        {
            int r0 = warp * 2, r1 = r0 + 1;
            float a0 = z[r0][lane], a1 = z[r0][lane + 32];
            float c0 = z[r1][lane], c1 = z[r1][lane + 32];
            float sA = a0 + a1,           sB = c0 + c1;
            float qA = a0 * a0 + a1 * a1, qB = c0 * c0 + c1 * c1;
#pragma unroll
            for (int o = 16; o; o >>= 1) {
                sA += __shfl_xor_sync(0xffffffffu, sA, o);
                sB += __shfl_xor_sync(0xffffffffu, sB, o);
                qA += __shfl_xor_sync(0xffffffffu, qA, o);
                qB += __shfl_xor_sync(0xffffffffu, qB, o);
            }
            float muA = sA * (1.0f / 64.0f), muB = sB * (1.0f / 64.0f);
            float rstdA = rsqrtf(fmaxf(qA * (1.0f / 64.0f) - muA * muA, 0.0f) + EPSC);
            float rstdB = rsqrtf(fmaxf(qB * (1.0f / 64.0f) - muB * muB, 0.0f) + EPSC);
            float w0 = lnw[lane], w1 = lnw[lane + 32];
            float bb0 = lnb[lane], bb1 = lnb[lane + 32];
            size_t go0 = base + (size_t)(n * MBSZ + r0) * WD;
            size_t go1 = base + (size_t)(n * MBSZ + r1) * WD;
            g_scan[go0 + lane]      = sxq[r0][lane]      + w0 * ((a0 - muA) * rstdA) + bb0;
            g_scan[go0 + lane + 32] = sxq[r0][lane + 32] + w1 * ((a1 - muA) * rstdA) + bb1;
            g_scan[go1 + lane]      = sxq[r1][lane]      + w0 * ((c0 - muB) * rstdB) + bb0;
            g_scan[go1 + lane + 32] = sxq[r1][lane + 32] + w1 * ((c1 - muB) * rstdB) + bb1;
        }

        // W1 update: 4 row-accumulators, single pass over j
        {
            float te = tok[15];
            int dr = ii * 4;
            float4 acc0 = *(const float4*)&W1[dr + 0][d0];
            float4 acc1 = *(const float4*)&W1[dr + 1][d0];
            float4 acc2 = *(const float4*)&W1[dr + 2][d0];
            float4 acc3 = *(const float4*)&W1[dr + 3][d0];
#pragma unroll
            for (int j = 0; j < 16; j++) {
                float lj = te * lr_sh[j];
                float4 gr  = *(const float4*)&grad[j][d0];
                float4 xk4 = *(const float4*)&sxk[j][dr];
                float c0 = lj * xk4.x, c1 = lj * xk4.y, c2 = lj * xk4.z, c3 = lj * xk4.w;
                acc0.x -= c0 * gr.x; acc0.y -= c0 * gr.y; acc0.z -= c0 * gr.z; acc0.w -= c0 * gr.w;
                acc1.x -= c1 * gr.x; acc1.y -= c1 * gr.y; acc1.z -= c1 * gr.z; acc1.w -= c1 * gr.w;
                acc2.x -= c2 * gr.x; acc2.y -= c2 * gr.y; acc2.z -= c2 * gr.z; acc2.w -= c2 * gr.w;
                acc3.x -= c3 * gr.x; acc3.y -= c3 * gr.y; acc3.z -= c3 * gr.z; acc3.w -= c3 * gr.w;
            }
            *(float4*)&W1[dr + 0][d0] = acc0;
            *(float4*)&W1[dr + 1][d0] = acc1;
            *(float4*)&W1[dr + 2][d0] = acc2;
            *(float4*)&W1[dr + 3][d0] = acc3;
            if (tid < 64) {
                float sm = 0.0f;
#pragma unroll
                for (int j = 0; j < 16; j++) sm += lr_sh[j] * grad[j][tid];
                b1[tid] -= te * sm;
            }
        }
        __syncthreads();
    }
}

// ---------------- post layer-norm fused with A split-fp16 conversion ----------------
__global__ __launch_bounds__(256) void ttt_postnorm_cvt(
    const float* __restrict__ pw, const float* __restrict__ pb)
{
    __shared__ float red[8];
    int bl = blockIdx.x, tid = threadIdx.x;
    int lane = tid & 31, warp = tid >> 5;
    const float4* src = (const float4*)(g_scan + (size_t)bl * WD);
    float4 v0 = src[tid], v1 = src[tid + 256];

    float s = v0.x + v0.y + v0.z + v0.w + v1.x + v1.y + v1.z + v1.w;
#pragma unroll
    for (int o = 16; o; o >>= 1) s += __shfl_xor_sync(0xffffffffu, s, o);
    if (lane == 0) red[warp] = s;
    __syncthreads();
    float tot = 0.0f;
#pragma unroll
    for (int i = 0; i < 8; i++) tot += red[i];
    float mu = tot * (1.0f / 2048.0f);
    __syncthreads();

    float q =
        (v0.x - mu) * (v0.x - mu) + (v0.y - mu) * (v0.y - mu) +
        (v0.z - mu) * (v0.z - mu) + (v0.w - mu) * (v0.w - mu) +
        (v1.x - mu) * (v1.x - mu) + (v1.y - mu) * (v1.y - mu) +
        (v1.z - mu) * (v1.z - mu) + (v1.w - mu) * (v1.w - mu);
#pragma unroll
    for (int o = 16; o; o >>= 1) q += __shfl_xor_sync(0xffffffffu, q, o);
    if (lane == 0) red[warp] = q;
    __syncthreads();
    float qt = 0.0f;
#pragma unroll
    for (int i = 0; i < 8; i++) qt += red[i];
    float rstd = rsqrtf(qt * (1.0f / 2048.0f) + EPSC);

    float4 w0 = ((const float4*)pw)[tid], w1 = ((const float4*)pw)[tid + 256];
    float4 b0 = ((const float4*)pb)[tid], b1v = ((const float4*)pb)[tid + 256];
    float4 o0, o1;
    o0.x = (v0.x - mu) * rstd * w0.x + b0.x;
    o0.y = (v0.y - mu) * rstd * w0.y + b0.y;
    o0.z = (v0.z - mu) * rstd * w0.z + b0.z;
    o0.w = (v0.w - mu) * rstd * w0.w + b0.w;
    o1.x = (v1.x - mu) * rstd * w1.x + b1v.x;
    o1.y = (v1.y - mu) * rstd * w1.y + b1v.y;
    o1.z = (v1.z - mu) * rstd * w1.z + b1v.z;
    o1.w = (v1.w - mu) * rstd * w1.w + b1v.w;

    size_t base0 = (size_t)bl * KP + (tid << 2);
    size_t base1 = (size_t)bl * KP + ((tid + 256) << 2);
    uint2 hi, lo;
    splitf16(o0, hi, lo);
    *(uint2*)(g_A_hf + base0)        = hi;
    *(uint2*)(g_A_hf + base0 + 2048) = lo;
    splitf16(o1, hi, lo);
    *(uint2*)(g_A_hf + base1)        = hi;
    *(uint2*)(g_A_hf + base1 + 2048) = lo;
}

// ---------------- launcher ----------------
extern "C" void kernel_launch(void* const* d_in, const int* in_sizes, int n_in,
                              void* d_out, int out_size)
{
    const float* hs  = (const float*)d_in[0];
    const float* q_w = (const float*)d_in[1];
    const float* v_w = (const float*)d_in[2];
    const float* o_w = (const float*)d_in[3];
    const float* cqw = (const float*)d_in[4];
    const float* cqb = (const float*)d_in[5];
    const float* ckw = (const float*)d_in[6];
    const float* ckb = (const float*)d_in[7];
    const float* lrw = (const float*)d_in[8];
    const float* lrb = (const float*)d_in[9];
    const float* lti = (const float*)d_in[10];
    const float* tnw = (const float*)d_in[11];
    const float* tnb = (const float*)d_in[12];
    const float* W1i = (const float*)d_in[13];
    const float* b1i = (const float*)d_in[14];
    const float* pnw = (const float*)d_in[15];
    const float* pnb = (const float*)d_in[16];
    float* out = (float*)d_out;

    static int smem_set = 0;
    if (!smem_set) {
        cudaFuncSetAttribute(ttt_hgemm, cudaFuncAttributeMaxDynamicSharedMemorySize, 2 * GS_STAGE);
        smem_set = 1;
    }

    // fused QV+lr projection: A=hs, B=[q_w; v_w; lr_w; pad]
    ttt_cvtA<<<16384, 256>>>(hs);
    ttt_cvtB<<<NROWS_B, 256>>>(q_w, v_w, lrw);
    ttt_hgemm<<<dim3(33, 64), 256, 2 * GS_STAGE>>>(nullptr, 1);   // -> g_xq, g_xv, g_lrraw

    // scan (conv+rope+lr fused inside)
    ttt_scan_kernel<<<BZ * NHD, 256>>>(lti, tnw, tnb, W1i, b1i, cqw, cqb, ckw, ckb, lrb);

    // B for final GEMM (stream-ordered after GEMM1 read g_B_hf)
    ttt_cvtB<<<2048, 256>>>(o_w, o_w, o_w);
    ttt_postnorm_cvt<<<BZ * LZ, 256>>>(pnw, pnb);                 // -> g_A_hf

    ttt_hgemm<<<dim3(16, 64), 256, 2 * GS_STAGE>>>(out, 0);
}

// round 15
// speedup vs baseline: 1.1372x; 1.0890x over previous
#include <cuda_runtime.h>
#include <cuda_fp16.h>
#include <math.h>
#include <stdint.h>

#define BZ 4
#define LZ 2048
#define WD 2048
#define NHD 32
#define HDM 64
#define MBSZ 16
#define NMBC 128
#define EPSC 1e-6f
#define ELEMS (BZ*LZ*WD)
#define KP 4096            // split-fp16 A: [hi | lo]
#define NROWS_B 4224       // 2048 q + 2048 v + 32 lr + 96 pad (33*128)

// ---------------- scratch (device globals; no allocation) ----------------
__device__ float g_xq[ELEMS];
__device__ float g_xv[ELEMS];
__device__ float g_scan[ELEMS];
__device__ float g_lrraw[8192 * 32];
__device__ __half g_A_hf[(size_t)8192 * KP];       // [hi | lo]
__device__ __half g_B_hf[(size_t)NROWS_B * 2048];  // hi plane only (dedup)

// ---------------- PTX helpers ----------------
__device__ __forceinline__ uint32_t smem_u32(const void* p) {
    uint32_t a;
    asm("{ .reg .u64 t; cvta.to.shared.u64 t, %1; cvt.u32.u64 %0, t; }" : "=r"(a) : "l"(p));
    return a;
}
#define CPA16(d, s) asm volatile("cp.async.cg.shared.global [%0], [%1], 16;" :: "r"(d), "l"(s) : "memory")
#define CPA4(d, s)  asm volatile("cp.async.ca.shared.global [%0], [%1], 4;"  :: "r"(d), "l"(s) : "memory")
#define CPA_COMMIT() asm volatile("cp.async.commit_group;" ::: "memory")
#define CPA_WAIT0()  asm volatile("cp.async.wait_group 0;" ::: "memory")

__device__ __forceinline__ void ldsm_x4(uint32_t a, uint32_t& r0, uint32_t& r1, uint32_t& r2, uint32_t& r3) {
    asm volatile("ldmatrix.sync.aligned.m8n8.x4.shared.b16 {%0,%1,%2,%3}, [%4];"
                 : "=r"(r0), "=r"(r1), "=r"(r2), "=r"(r3) : "r"(a));
}
__device__ __forceinline__ void mma_f16(float* c, const uint32_t* a, const uint32_t* b) {
    asm volatile("mma.sync.aligned.m16n8k16.row.col.f32.f16.f16.f32 "
                 "{%0,%1,%2,%3}, {%4,%5,%6,%7}, {%8,%9}, {%0,%1,%2,%3};"
                 : "+f"(c[0]), "+f"(c[1]), "+f"(c[2]), "+f"(c[3])
                 : "r"(a[0]), "r"(a[1]), "r"(a[2]), "r"(a[3]), "r"(b[0]), "r"(b[1]));
}

// ---------------- split-fp16 helpers ----------------
__device__ __forceinline__ void splitf16(const float4& v, uint2& hi, uint2& lo) {
    __half2 h01 = __floats2half2_rn(v.x, v.y);
    __half2 h23 = __floats2half2_rn(v.z, v.w);
    float2 f01 = __half22float2(h01), f23 = __half22float2(h23);
    __half2 l01 = __floats2half2_rn(v.x - f01.x, v.y - f01.y);
    __half2 l23 = __floats2half2_rn(v.z - f23.x, v.w - f23.y);
    hi.x = *(uint32_t*)&h01; hi.y = *(uint32_t*)&h23;
    lo.x = *(uint32_t*)&l01; lo.y = *(uint32_t*)&l23;
}

// ---------------- A conversion: fp32 [8192,2048] -> fp16 [8192,4096] = [hi|lo] ----------------
__global__ __launch_bounds__(256) void ttt_cvtA(const float* __restrict__ src)
{
    int t = blockIdx.x * 256 + threadIdx.x;
    float4 v = ((const float4*)src)[t];
    int r = t >> 9, c4 = t & 511;
    size_t base = (size_t)r * KP + (c4 << 2);
    uint2 hi, lo;
    splitf16(v, hi, lo);
    *(uint2*)(g_A_hf + base)        = hi;
    *(uint2*)(g_A_hf + base + 2048) = lo;
}

// ---------------- B conversion (3 sources + zero pad): hi plane only ----------------
__global__ __launch_bounds__(256) void ttt_cvtB(const float* __restrict__ w0,
                                                const float* __restrict__ w1,
                                                const float* __restrict__ w2)
{
    int row = blockIdx.x;
    int tid = threadIdx.x;
    const float* srcp = nullptr;
    if (row < 2048) srcp = w0 + (size_t)row * 2048;
    else if (row < 4096) srcp = w1 + (size_t)(row - 2048) * 2048;
    else if (row < 4128) srcp = w2 + (size_t)(row - 4096) * 2048;
    float4 v0 = make_float4(0, 0, 0, 0), v1 = v0;
    if (srcp) { v0 = ((const float4*)srcp)[tid]; v1 = ((const float4*)srcp)[tid + 256]; }
    uint2 hi, lo;
    splitf16(v0, hi, lo);
    *(uint2*)(g_B_hf + (size_t)row * 2048 + (tid << 2)) = hi;
    splitf16(v1, hi, lo);
    *(uint2*)(g_B_hf + (size_t)row * 2048 + ((tid + 256) << 2)) = hi;
}

// ---------------- fp16 mma.sync GEMM: 128x128, 256 thr, B-dedup, 2-stage x 48KB ----------------
#define GS_STAGE 49152
#define GKSTEPS 32
__global__ __launch_bounds__(256, 2) void ttt_hgemm(float* Cext, int fused)
{
    extern __shared__ char smem[];
    uint32_t sb = smem_u32(smem);
    const int tid = threadIdx.x;
    const int wid = tid >> 5, lane = tid & 31;
    const int m0 = blockIdx.y << 7;
    const int n0 = blockIdx.x << 7;
    const int mw = (wid >> 2) << 6;
    const int nw = (wid & 3) << 5;

    const __half* Ab = g_A_hf + (size_t)m0 * KP;
    const __half* Bb = g_B_hf + (size_t)n0 * 2048;

    float acc[4][4][4];
#pragma unroll
    for (int i = 0; i < 4; i++)
#pragma unroll
        for (int j = 0; j < 4; j++)
#pragma unroll
            for (int q = 0; q < 4; q++) acc[i][j][q] = 0.0f;

    auto load_stage = [&](int s, int kt) {
        uint32_t sAh = sb + s * GS_STAGE;
        uint32_t sAl = sAh + 16384;
        uint32_t sB  = sAh + 32768;
#pragma unroll
        for (int i = 0; i < 4; i++) {
            int idx = tid + (i << 8);
            int row = idx >> 3, c = idx & 7;
            uint32_t soff = (uint32_t)(row << 7) + (((uint32_t)(c ^ (row & 7))) << 4);
            const __half* ar = Ab + (size_t)row * KP + kt * 64 + c * 8;
            CPA16(sAh + soff, (const char*)ar);
            CPA16(sAl + soff, (const char*)(ar + 2048));
            CPA16(sB + soff, (const char*)(Bb + (size_t)row * 2048 + kt * 64 + c * 8));
        }
        CPA_COMMIT();
    };

    load_stage(0, 0);
    const int lr15 = lane & 15, lhi = lane >> 4;

    for (int kt = 0; kt < GKSTEPS; kt++) {
        int s = kt & 1;
        if (kt + 1 < GKSTEPS) {
            load_stage(s ^ 1, kt + 1);
            asm volatile("cp.async.wait_group 1;" ::: "memory");
        } else {
            CPA_WAIT0();
        }
        __syncthreads();

        uint32_t aH = sb + s * GS_STAGE;
        uint32_t aL = aH + 16384;
        uint32_t bB = aH + 32768;
#pragma unroll
        for (int ks = 0; ks < 4; ks++) {
            uint32_t bf[4][2];
#pragma unroll
            for (int np = 0; np < 2; np++) {
                int row = nw + np * 16 + lr15;
                uint32_t bd = bB + (uint32_t)(row << 7) + ((uint32_t)((2 * ks + lhi) ^ (row & 7)) << 4);
                uint32_t r0, r1, r2, r3;
                ldsm_x4(bd, r0, r1, r2, r3);
                bf[np * 2][0] = r0;     bf[np * 2][1] = r2;
                bf[np * 2 + 1][0] = r1; bf[np * 2 + 1][1] = r3;
            }
            uint32_t af[4][4];
#pragma unroll
            for (int mt = 0; mt < 4; mt++) {
                int row = mw + mt * 16 + lr15;
                uint32_t ad = aH + (uint32_t)(row << 7) + ((uint32_t)((2 * ks + lhi) ^ (row & 7)) << 4);
                ldsm_x4(ad, af[mt][0], af[mt][1], af[mt][2], af[mt][3]);
            }
#pragma unroll
            for (int mt = 0; mt < 4; mt++)
#pragma unroll
                for (int nt = 0; nt < 4; nt++)
                    mma_f16(acc[mt][nt], af[mt], bf[nt]);
#pragma unroll
            for (int mt = 0; mt < 4; mt++) {
                int row = mw + mt * 16 + lr15;
                uint32_t ad = aL + (uint32_t)(row << 7) + ((uint32_t)((2 * ks + lhi) ^ (row & 7)) << 4);
                ldsm_x4(ad, af[mt][0], af[mt][1], af[mt][2], af[mt][3]);
            }
#pragma unroll
            for (int mt = 0; mt < 4; mt++)
#pragma unroll
                for (int nt = 0; nt < 4; nt++)
                    mma_f16(acc[mt][nt], af[mt], bf[nt]);
        }
        __syncthreads();
    }

#pragma unroll
    for (int mt = 0; mt < 4; mt++) {
#pragma unroll
        for (int nt = 0; nt < 4; nt++) {
            int col = n0 + nw + nt * 8 + (lane & 3) * 2;
            int row = m0 + mw + mt * 16 + (lane >> 2);
            float2 va = make_float2(acc[mt][nt][0], acc[mt][nt][1]);
            float2 vb = make_float2(acc[mt][nt][2], acc[mt][nt][3]);
            if (!fused) {
                *(float2*)(Cext + (size_t)row * 2048 + col) = va;
                *(float2*)(Cext + (size_t)(row + 8) * 2048 + col) = vb;
            } else if (col < 2048) {
                *(float2*)(g_xq + (size_t)row * 2048 + col) = va;
                *(float2*)(g_xq + (size_t)(row + 8) * 2048 + col) = vb;
            } else if (col < 4096) {
                *(float2*)(g_xv + (size_t)row * 2048 + col - 2048) = va;
                *(float2*)(g_xv + (size_t)(row + 8) * 2048 + col - 2048) = vb;
            } else if (col < 4128) {
                *(float2*)(g_lrraw + (size_t)row * 32 + col - 4096) = va;
                *(float2*)(g_lrraw + (size_t)(row + 8) * 32 + col - 4096) = vb;
            }
        }
    }
}

// ---------------- TTT scan: merged dual matmul, hoisted invariants ----------------
__global__ __launch_bounds__(256) void ttt_scan_kernel(
    const float* __restrict__ lt_idx,
    const float* __restrict__ lnw_g, const float* __restrict__ lnb_g,
    const float* __restrict__ W1g,   const float* __restrict__ b1g,
    const float* __restrict__ cqw,   const float* __restrict__ cqb,
    const float* __restrict__ ckw,   const float* __restrict__ ckb,
    const float* __restrict__ lrb)
{
    __shared__ float W1[64][64];
    __shared__ float sraw[2][19][68];
    __shared__ float sxv[2][16][68];
    __shared__ float sxq[16][68], sxk[16][68];
    __shared__ float grad[16][68], z[16][68];
    __shared__ float attn[16][16];
    __shared__ float wq_s[256], wk_s[256];
    __shared__ float bq_s[64], bk_s[64];
    __shared__ float b1[64], lnw[64], lnb[64];
    __shared__ float lrrawbuf[2][16], lr_sh[16], tok[16];

    int tid = threadIdx.x;
    int b = blockIdx.x >> 5, h = blockIdx.x & 31;
    const int ch0 = h * 64;

    for (int o = tid; o < 4096; o += 256)
        ((float*)W1)[o] = W1g[(size_t)h * 4096 + o];
    if (tid < 64) {
        b1[tid]  = b1g[h * 64 + tid];
        lnw[tid] = lnw_g[h * 64 + tid];
        lnb[tid] = lnb_g[h * 64 + tid];
        bq_s[tid] = cqb[ch0 + tid];
        bk_s[tid] = ckb[ch0 + tid];
    }
    wq_s[tid] = cqw[ch0 * 4 + tid];
    wk_s[tid] = ckw[ch0 * 4 + tid];
    if (tid < 16) tok[tid] = fmaxf(1.0f / (float)(tid + 1) + lt_idx[tid], 0.0f);
    for (int o = tid; o < 2 * 19 * 68; o += 256)
        ((float*)sraw)[o] = 0.0f;

    const int warp = tid >> 5, lane = tid & 31;
    const int ii = tid >> 4;
    const int d0 = (tid & 15) * 4;
    const size_t base = ((size_t)b * LZ) * WD + (size_t)ch0;
    const float lrb_h = lrb[h];

    float cs0, sn0, cs1, sn1;
    {
        int i0 = d0 >> 1;
        float inv0 = exp2f(-(float)i0 * (13.2877123795f / 32.0f));
        float inv1 = exp2f(-(float)(i0 + 1) * (13.2877123795f / 32.0f));
        sincosf((float)ii * inv0, &sn0, &cs0);
        sincosf((float)ii * inv1, &sn1, &cs1);
    }
    __syncthreads();

    // loop-invariant registers (after init sync)
    const float w0_r = lnw[lane], w1_r = lnw[lane + 32];
    const float bb0_r = lnb[lane], bb1_r = lnb[lane + 32];
    const float tok_ii = tok[ii];
    const float te = tok[15];

    const uint32_t a_raw = smem_u32(&sraw[0][0][0]);
    const uint32_t a_xv  = smem_u32(&sxv[0][0][0]);
    const uint32_t a_lrr = smem_u32(&lrrawbuf[0][0]);
    const uint32_t RAWB = 19 * 68 * 4;
    const uint32_t XVB  = 16 * 68 * 4;

    auto prefetch = [&](int s, int n) {
#pragma unroll
        for (int it = 0; it < 2; it++) {
            int idx = tid + (it << 8);
            if (idx < 304) {
                int row = idx >> 4, c = idx & 15;
                int g = n * MBSZ - 3 + row;
                if (g >= 0)
                    CPA16(a_raw + s * RAWB + (uint32_t)(row * 272 + c * 16),
                          (const char*)&g_xq[base + (size_t)g * WD + c * 4]);
            }
        }
        {
            int row = tid >> 4, c = tid & 15;
            CPA16(a_xv + s * XVB + (uint32_t)(row * 272 + c * 16),
                  (const char*)&g_xv[base + (size_t)(n * MBSZ + row) * WD + c * 4]);
        }
        if (tid < 16)
            CPA4(a_lrr + s * 64 + tid * 4,
                 (const char*)&g_lrraw[((size_t)b * LZ + n * MBSZ + tid) * 32 + h]);
        CPA_COMMIT();
    };

    prefetch(0, 0);

    for (int n = 0; n < NMBC; n++) {
        const int s = n & 1;
        CPA_WAIT0();
        __syncthreads();
        if (n + 1 < NMBC) prefetch(s ^ 1, n + 1);

        // conv + rope
        {
            float4 t0 = *(const float4*)&sraw[s][ii + 0][d0];
            float4 t1 = *(const float4*)&sraw[s][ii + 1][d0];
            float4 t2 = *(const float4*)&sraw[s][ii + 2][d0];
            float4 t3 = *(const float4*)&sraw[s][ii + 3][d0];
            const float* ta = (const float*)&t0;
            const float* tb = (const float*)&t1;
            const float* tc = (const float*)&t2;
            const float* td = (const float*)&t3;
            float qv[4], kv[4];
#pragma unroll
            for (int d = 0; d < 4; d++) {
                int ch = d0 + d;
                qv[d] = bq_s[ch] + ta[d] * wq_s[ch * 4] + tb[d] * wq_s[ch * 4 + 1]
                                 + tc[d] * wq_s[ch * 4 + 2] + td[d] * wq_s[ch * 4 + 3];
                kv[d] = bk_s[ch] + ta[d] * wk_s[ch * 4] + tb[d] * wk_s[ch * 4 + 1]
                                 + tc[d] * wk_s[ch * 4 + 2] + td[d] * wk_s[ch * 4 + 3];
            }
            float4 oq, ok;
            oq.x = qv[0] * cs0 - qv[1] * sn0;  oq.y = qv[1] * cs0 + qv[0] * sn0;
            oq.z = qv[2] * cs1 - qv[3] * sn1;  oq.w = qv[3] * cs1 + qv[2] * sn1;
            ok.x = kv[0] * cs0 - kv[1] * sn0;  ok.y = kv[1] * cs0 + kv[0] * sn0;
            ok.z = kv[2] * cs1 - kv[3] * sn1;  ok.w = kv[3] * cs1 + kv[2] * sn1;
            *(float4*)&sxq[ii][d0] = oq;
            *(float4*)&sxk[ii][d0] = ok;
        }
        if (tid < 16)
            lr_sh[tid] = (1.0f / 64.0f) / (1.0f + expf(-(lrrawbuf[s][tid] + lrb_h)));
        __syncthreads();

        // merged dual matmul: z_k = xk@W1+b1 -> smem; z_q = xq@W1+b1 -> regs
        float4 accq;
        {
            float4 acck = *(const float4*)&b1[d0];
            accq = acck;
#pragma unroll
            for (int e4 = 0; e4 < 16; e4++) {
                float4 xk4 = *(const float4*)&sxk[ii][e4 * 4];
                float4 xq4 = *(const float4*)&sxq[ii][e4 * 4];
                float4 w;
                w = *(const float4*)&W1[e4 * 4 + 0][d0];
                acck.x += xk4.x * w.x; acck.y += xk4.x * w.y; acck.z += xk4.x * w.z; acck.w += xk4.x * w.w;
                accq.x += xq4.x * w.x; accq.y += xq4.x * w.y; accq.z += xq4.x * w.z; accq.w += xq4.x * w.w;
                w = *(const float4*)&W1[e4 * 4 + 1][d0];
                acck.x += xk4.y * w.x; acck.y += xk4.y * w.y; acck.z += xk4.y * w.z; acck.w += xk4.y * w.w;
                accq.x += xq4.y * w.x; accq.y += xq4.y * w.y; accq.z += xq4.y * w.z; accq.w += xq4.y * w.w;
                w = *(const float4*)&W1[e4 * 4 + 2][d0];
                acck.x += xk4.z * w.x; acck.y += xk4.z * w.y; acck.z += xk4.z * w.z; acck.w += xk4.z * w.w;
                accq.x += xq4.z * w.x; accq.y += xq4.z * w.y; accq.z += xq4.z * w.z; accq.w += xq4.z * w.w;
                w = *(const float4*)&W1[e4 * 4 + 3][d0];
                acck.x += xk4.w * w.x; acck.y += xk4.w * w.y; acck.z += xk4.w * w.z; acck.w += xk4.w * w.w;
                accq.x += xq4.w * w.x; accq.y += xq4.w * w.y; accq.z += xq4.w * w.z; accq.w += xq4.w * w.w;
            }
            *(float4*)&z[ii][d0] = acck;
        }
        // attn (float4 dot)
        {
            int i = tid >> 4, j = tid & 15;
            const float4* qa = (const float4*)&sxq[i][0];
            const float4* ka = (const float4*)&sxk[j][0];
            float sa = 0.0f;
#pragma unroll
            for (int d4 = 0; d4 < 16; d4++) {
                float4 a = qa[d4], c = ka[d4];
                sa += a.x * c.x + a.y * c.y + a.z * c.z + a.w * c.w;
            }
            attn[i][j] = sa;
        }
        __syncthreads();

        // grad = ln_l2_bwd(Z1, xv-xk): both rows at once, fused sum+sumsq
        {
            int r0 = warp * 2, r1 = r0 + 1;
            float a0 = z[r0][lane], a1 = z[r0][lane + 32];
            float c0 = z[r1][lane], c1 = z[r1][lane + 32];
            float sA = a0 + a1,           sB = c0 + c1;
            float qA = a0 * a0 + a1 * a1, qB = c0 * c0 + c1 * c1;
#pragma unroll
            for (int o = 16; o; o >>= 1) {
                sA += __shfl_xor_sync(0xffffffffu, sA, o);
                sB += __shfl_xor_sync(0xffffffffu, sB, o);
                qA += __shfl_xor_sync(0xffffffffu, qA, o);
                qB += __shfl_xor_sync(0xffffffffu, qB, o);
            }
            float muA = sA * (1.0f / 64.0f), muB = sB * (1.0f / 64.0f);
            float rstdA = rsqrtf(fmaxf(qA * (1.0f / 64.0f) - muA * muA, 0.0f) + EPSC);
            float rstdB = rsqrtf(fmaxf(qB * (1.0f / 64.0f) - muB * muB, 0.0f) + EPSC);
            float xhA0 = (a0 - muA) * rstdA, xhA1 = (a1 - muA) * rstdA;
            float xhB0 = (c0 - muB) * rstdB, xhB1 = (c1 - muB) * rstdB;
            float tA0 = sxv[s][r0][lane] - sxk[r0][lane];
            float tA1 = sxv[s][r0][lane + 32] - sxk[r0][lane + 32];
            float tB0 = sxv[s][r1][lane] - sxk[r1][lane];
            float tB1 = sxv[s][r1][lane + 32] - sxk[r1][lane + 32];
            float gyA0 = (w0_r * xhA0 + bb0_r - tA0) * w0_r;
            float gyA1 = (w1_r * xhA1 + bb1_r - tA1) * w1_r;
            float gyB0 = (w0_r * xhB0 + bb0_r - tB0) * w0_r;
            float gyB1 = (w1_r * xhB1 + bb1_r - tB1) * w1_r;
            float u1A = gyA0 + gyA1, u2A = gyA0 * xhA0 + gyA1 * xhA1;
            float u1B = gyB0 + gyB1, u2B = gyB0 * xhB0 + gyB1 * xhB1;
#pragma unroll
            for (int o = 16; o; o >>= 1) {
                u1A += __shfl_xor_sync(0xffffffffu, u1A, o);
                u2A += __shfl_xor_sync(0xffffffffu, u2A, o);
                u1B += __shfl_xor_sync(0xffffffffu, u1B, o);
                u2B += __shfl_xor_sync(0xffffffffu, u2B, o);
            }
            float scA = rstdA * (1.0f / 64.0f), scB = rstdB * (1.0f / 64.0f);
            grad[r0][lane]      = (64.0f * gyA0 - u1A - xhA0 * u2A) * scA;
            grad[r0][lane + 32] = (64.0f * gyA1 - u1A - xhA1 * u2A) * scA;
            grad[r1][lane]      = (64.0f * gyB0 - u1B - xhB0 * u2B) * scB;
            grad[r1][lane + 32] = (64.0f * gyB1 - u1B - xhB1 * u2B) * scB;
        }
        __syncthreads();

        // Z1_bar finalize (register accumulator + grad correction)
        {
            for (int j = 0; j <= ii; j++) {
                float cf = tok_ii * lr_sh[j] * (attn[ii][j] + 1.0f);
                float4 gr = *(const float4*)&grad[j][d0];
                accq.x -= cf * gr.x; accq.y -= cf * gr.y; accq.z -= cf * gr.z; accq.w -= cf * gr.w;
            }
            *(float4*)&z[ii][d0] = accq;
        }
        __syncthreads();

        // out = xq + ln_fwd(Z1_bar): both rows at once
        {
            int r0 = warp * 2, r1 = r0 + 1;
            float a0 = z[r0][lane], a1 = z[r0][lane + 32];
            float c0 = z[r1][lane], c1 = z[r1][lane + 32];
            float sA = a0 + a1,           sB = c0 + c1;
            float qA = a0 * a0 + a1 * a1, qB = c0 * c0 + c1 * c1;
#pragma unroll
            for (int o = 16; o; o >>= 1) {
                sA += __shfl_xor_sync(0xffffffffu, sA, o);
                sB += __shfl_xor_sync(0xffffffffu, sB, o);
                qA += __shfl_xor_sync(0xffffffffu, qA, o);
                qB += __shfl_xor_sync(0xffffffffu, qB, o);
            }
            float muA = sA * (1.0f / 64.0f), muB = sB * (1.0f / 64.0f);
            float rstdA = rsqrtf(fmaxf(qA * (1.0f / 64.0f) - muA * muA, 0.0f) + EPSC);
            float rstdB = rsqrtf(fmaxf(qB * (1.0f / 64.0f) - muB * muB, 0.0f) + EPSC);
            size_t go0 = base + (size_t)(n * MBSZ + r0) * WD;
            size_t go1 = base + (size_t)(n * MBSZ + r1) * WD;
            g_scan[go0 + lane]      = sxq[r0][lane]      + w0_r * ((a0 - muA) * rstdA) + bb0_r;
            g_scan[go0 + lane + 32] = sxq[r0][lane + 32] + w1_r * ((a1 - muA) * rstdA) + bb1_r;
            g_scan[go1 + lane]      = sxq[r1][lane]      + w0_r * ((c0 - muB) * rstdB) + bb0_r;
            g_scan[go1 + lane + 32] = sxq[r1][lane + 32] + w1_r * ((c1 - muB) * rstdB) + bb1_r;
        }

        // W1 update: 4 row-accumulators, single pass over j
        {
            int dr = ii * 4;
            float4 acc0 = *(const float4*)&W1[dr + 0][d0];
            float4 acc1 = *(const float4*)&W1[dr + 1][d0];
            float4 acc2 = *(const float4*)&W1[dr + 2][d0];
            float4 acc3 = *(const float4*)&W1[dr + 3][d0];
#pragma unroll
            for (int j = 0; j < 16; j++) {
                float lj = te * lr_sh[j];
                float4 gr  = *(const float4*)&grad[j][d0];
                float4 xk4 = *(const float4*)&sxk[j][dr];
                float c0 = lj * xk4.x, c1 = lj * xk4.y, c2 = lj * xk4.z, c3 = lj * xk4.w;
                acc0.x -= c0 * gr.x; acc0.y -= c0 * gr.y; acc0.z -= c0 * gr.z; acc0.w -= c0 * gr.w;
                acc1.x -= c1 * gr.x; acc1.y -= c1 * gr.y; acc1.z -= c1 * gr.z; acc1.w -= c1 * gr.w;
                acc2.x -= c2 * gr.x; acc2.y -= c2 * gr.y; acc2.z -= c2 * gr.z; acc2.w -= c2 * gr.w;
                acc3.x -= c3 * gr.x; acc3.y -= c3 * gr.y; acc3.z -= c3 * gr.z; acc3.w -= c3 * gr.w;
            }
            *(float4*)&W1[dr + 0][d0] = acc0;
            *(float4*)&W1[dr + 1][d0] = acc1;
            *(float4*)&W1[dr + 2][d0] = acc2;
            *(float4*)&W1[dr + 3][d0] = acc3;
            if (tid < 64) {
                float sm = 0.0f;
#pragma unroll
                for (int j = 0; j < 16; j++) sm += lr_sh[j] * grad[j][tid];
                b1[tid] -= te * sm;
            }
        }
        __syncthreads();
    }
}

// ---------------- post layer-norm fused with A split-fp16 conversion ----------------
__global__ __launch_bounds__(256) void ttt_postnorm_cvt(
    const float* __restrict__ pw, const float* __restrict__ pb)
{
    __shared__ float red[8];
    int bl = blockIdx.x, tid = threadIdx.x;
    int lane = tid & 31, warp = tid >> 5;
    const float4* src = (const float4*)(g_scan + (size_t)bl * WD);
    float4 v0 = src[tid], v1 = src[tid + 256];

    float s = v0.x + v0.y + v0.z + v0.w + v1.x + v1.y + v1.z + v1.w;
#pragma unroll
    for (int o = 16; o; o >>= 1) s += __shfl_xor_sync(0xffffffffu, s, o);
    if (lane == 0) red[warp] = s;
    __syncthreads();
    float tot = 0.0f;
#pragma unroll
    for (int i = 0; i < 8; i++) tot += red[i];
    float mu = tot * (1.0f / 2048.0f);
    __syncthreads();

    float q =
        (v0.x - mu) * (v0.x - mu) + (v0.y - mu) * (v0.y - mu) +
        (v0.z - mu) * (v0.z - mu) + (v0.w - mu) * (v0.w - mu) +
        (v1.x - mu) * (v1.x - mu) + (v1.y - mu) * (v1.y - mu) +
        (v1.z - mu) * (v1.z - mu) + (v1.w - mu) * (v1.w - mu);
#pragma unroll
    for (int o = 16; o; o >>= 1) q += __shfl_xor_sync(0xffffffffu, q, o);
    if (lane == 0) red[warp] = q;
    __syncthreads();
    float qt = 0.0f;
#pragma unroll
    for (int i = 0; i < 8; i++) qt += red[i];
    float rstd = rsqrtf(qt * (1.0f / 2048.0f) + EPSC);

    float4 w0 = ((const float4*)pw)[tid], w1 = ((const float4*)pw)[tid + 256];
    float4 b0 = ((const float4*)pb)[tid], b1v = ((const float4*)pb)[tid + 256];
    float4 o0, o1;
    o0.x = (v0.x - mu) * rstd * w0.x + b0.x;
    o0.y = (v0.y - mu) * rstd * w0.y + b0.y;
    o0.z = (v0.z - mu) * rstd * w0.z + b0.z;
    o0.w = (v0.w - mu) * rstd * w0.w + b0.w;
    o1.x = (v1.x - mu) * rstd * w1.x + b1v.x;
    o1.y = (v1.y - mu) * rstd * w1.y + b1v.y;
    o1.z = (v1.z - mu) * rstd * w1.z + b1v.z;
    o1.w = (v1.w - mu) * rstd * w1.w + b1v.w;

    size_t base0 = (size_t)bl * KP + (tid << 2);
    size_t base1 = (size_t)bl * KP + ((tid + 256) << 2);
    uint2 hi, lo;
    splitf16(o0, hi, lo);
    *(uint2*)(g_A_hf + base0)        = hi;
    *(uint2*)(g_A_hf + base0 + 2048) = lo;
    splitf16(o1, hi, lo);
    *(uint2*)(g_A_hf + base1)        = hi;
    *(uint2*)(g_A_hf + base1 + 2048) = lo;
}

// ---------------- launcher ----------------
extern "C" void kernel_launch(void* const* d_in, const int* in_sizes, int n_in,
                              void* d_out, int out_size)
{
    const float* hs  = (const float*)d_in[0];
    const float* q_w = (const float*)d_in[1];
    const float* v_w = (const float*)d_in[2];
    const float* o_w = (const float*)d_in[3];
    const float* cqw = (const float*)d_in[4];
    const float* cqb = (const float*)d_in[5];
    const float* ckw = (const float*)d_in[6];
    const float* ckb = (const float*)d_in[7];
    const float* lrw = (const float*)d_in[8];
    const float* lrb = (const float*)d_in[9];
    const float* lti = (const float*)d_in[10];
    const float* tnw = (const float*)d_in[11];
    const float* tnb = (const float*)d_in[12];
    const float* W1i = (const float*)d_in[13];
    const float* b1i = (const float*)d_in[14];
    const float* pnw = (const float*)d_in[15];
    const float* pnb = (const float*)d_in[16];
    float* out = (float*)d_out;

    static int smem_set = 0;
    if (!smem_set) {
        cudaFuncSetAttribute(ttt_hgemm, cudaFuncAttributeMaxDynamicSharedMemorySize, 2 * GS_STAGE);
        smem_set = 1;
    }

    // fused QV+lr projection: A=hs, B=[q_w; v_w; lr_w; pad]
    ttt_cvtA<<<16384, 256>>>(hs);
    ttt_cvtB<<<NROWS_B, 256>>>(q_w, v_w, lrw);
    ttt_hgemm<<<dim3(33, 64), 256, 2 * GS_STAGE>>>(nullptr, 1);   // -> g_xq, g_xv, g_lrraw

    // scan (conv+rope+lr fused inside)
    ttt_scan_kernel<<<BZ * NHD, 256>>>(lti, tnw, tnb, W1i, b1i, cqw, cqb, ckw, ckb, lrb);

    // B for final GEMM (stream-ordered after GEMM1 read g_B_hf)
    ttt_cvtB<<<2048, 256>>>(o_w, o_w, o_w);
    ttt_postnorm_cvt<<<BZ * LZ, 256>>>(pnw, pnb);                 // -> g_A_hf

    ttt_hgemm<<<dim3(16, 64), 256, 2 * GS_STAGE>>>(out, 0);
}

// round 16
// speedup vs baseline: 1.1652x; 1.0246x over previous
#include <cuda_runtime.h>
#include <cuda_fp16.h>
#include <math.h>
#include <stdint.h>

#define BZ 4
#define LZ 2048
#define WD 2048
#define NHD 32
#define HDM 64
#define MBSZ 16
#define NMBC 128
#define EPSC 1e-6f
#define ELEMS (BZ*LZ*WD)
#define KP 4096            // split-fp16 A: [hi | lo]
#define NROWS_B 4224       // 2048 q + 2048 v + 32 lr + 96 pad (33*128)

// ---------------- scratch (device globals; no allocation) ----------------
__device__ float g_xq[ELEMS];
__device__ float g_xv[ELEMS];
__device__ float g_scan[ELEMS];
__device__ float g_lrraw[8192 * 32];
__device__ __half g_A_hf[(size_t)8192 * KP];       // [hi | lo]
__device__ __half g_B_hf[(size_t)NROWS_B * 2048];  // hi plane only (dedup)

// ---------------- PTX helpers ----------------
__device__ __forceinline__ uint32_t smem_u32(const void* p) {
    uint32_t a;
    asm("{ .reg .u64 t; cvta.to.shared.u64 t, %1; cvt.u32.u64 %0, t; }" : "=r"(a) : "l"(p));
    return a;
}
#define CPA16(d, s) asm volatile("cp.async.cg.shared.global [%0], [%1], 16;" :: "r"(d), "l"(s) : "memory")
#define CPA4(d, s)  asm volatile("cp.async.ca.shared.global [%0], [%1], 4;"  :: "r"(d), "l"(s) : "memory")
#define CPA_COMMIT() asm volatile("cp.async.commit_group;" ::: "memory")
#define CPA_WAIT0()  asm volatile("cp.async.wait_group 0;" ::: "memory")

__device__ __forceinline__ void ldsm_x4(uint32_t a, uint32_t& r0, uint32_t& r1, uint32_t& r2, uint32_t& r3) {
    asm volatile("ldmatrix.sync.aligned.m8n8.x4.shared.b16 {%0,%1,%2,%3}, [%4];"
                 : "=r"(r0), "=r"(r1), "=r"(r2), "=r"(r3) : "r"(a));
}
__device__ __forceinline__ void mma_f16(float* c, const uint32_t* a, const uint32_t* b) {
    asm volatile("mma.sync.aligned.m16n8k16.row.col.f32.f16.f16.f32 "
                 "{%0,%1,%2,%3}, {%4,%5,%6,%7}, {%8,%9}, {%0,%1,%2,%3};"
                 : "+f"(c[0]), "+f"(c[1]), "+f"(c[2]), "+f"(c[3])
                 : "r"(a[0]), "r"(a[1]), "r"(a[2]), "r"(a[3]), "r"(b[0]), "r"(b[1]));
}

// ---------------- split-fp16 helpers ----------------
__device__ __forceinline__ void splitf16(const float4& v, uint2& hi, uint2& lo) {
    __half2 h01 = __floats2half2_rn(v.x, v.y);
    __half2 h23 = __floats2half2_rn(v.z, v.w);
    float2 f01 = __half22float2(h01), f23 = __half22float2(h23);
    __half2 l01 = __floats2half2_rn(v.x - f01.x, v.y - f01.y);
    __half2 l23 = __floats2half2_rn(v.z - f23.x, v.w - f23.y);
    hi.x = *(uint32_t*)&h01; hi.y = *(uint32_t*)&h23;
    lo.x = *(uint32_t*)&l01; lo.y = *(uint32_t*)&l23;
}

// ---------------- A conversion: fp32 [8192,2048] -> fp16 [8192,4096] = [hi|lo] ----------------
__global__ __launch_bounds__(256) void ttt_cvtA(const float* __restrict__ src)
{
    int t = blockIdx.x * 256 + threadIdx.x;
    float4 v = ((const float4*)src)[t];
    int r = t >> 9, c4 = t & 511;
    size_t base = (size_t)r * KP + (c4 << 2);
    uint2 hi, lo;
    splitf16(v, hi, lo);
    *(uint2*)(g_A_hf + base)        = hi;
    *(uint2*)(g_A_hf + base + 2048) = lo;
}

// ---------------- B conversion (3 sources + zero pad): hi plane only ----------------
__global__ __launch_bounds__(256) void ttt_cvtB(const float* __restrict__ w0,
                                                const float* __restrict__ w1,
                                                const float* __restrict__ w2)
{
    int row = blockIdx.x;
    int tid = threadIdx.x;
    const float* srcp = nullptr;
    if (row < 2048) srcp = w0 + (size_t)row * 2048;
    else if (row < 4096) srcp = w1 + (size_t)(row - 2048) * 2048;
    else if (row < 4128) srcp = w2 + (size_t)(row - 4096) * 2048;
    float4 v0 = make_float4(0, 0, 0, 0), v1 = v0;
    if (srcp) { v0 = ((const float4*)srcp)[tid]; v1 = ((const float4*)srcp)[tid + 256]; }
    uint2 hi, lo;
    splitf16(v0, hi, lo);
    *(uint2*)(g_B_hf + (size_t)row * 2048 + (tid << 2)) = hi;
    splitf16(v1, hi, lo);
    *(uint2*)(g_B_hf + (size_t)row * 2048 + ((tid + 256) << 2)) = hi;
}

// ---------------- fp16 mma.sync GEMM: 128x128, 256 thr, B-dedup, 2-stage x 48KB ----------------
#define GS_STAGE 49152
#define GKSTEPS 32
__global__ __launch_bounds__(256, 2) void ttt_hgemm(float* Cext, int fused)
{
    extern __shared__ char smem[];
    uint32_t sb = smem_u32(smem);
    const int tid = threadIdx.x;
    const int wid = tid >> 5, lane = tid & 31;
    const int m0 = blockIdx.y << 7;
    const int n0 = blockIdx.x << 7;
    const int mw = (wid >> 2) << 6;
    const int nw = (wid & 3) << 5;

    const __half* Ab = g_A_hf + (size_t)m0 * KP;
    const __half* Bb = g_B_hf + (size_t)n0 * 2048;

    float acc[4][4][4];
#pragma unroll
    for (int i = 0; i < 4; i++)
#pragma unroll
        for (int j = 0; j < 4; j++)
#pragma unroll
            for (int q = 0; q < 4; q++) acc[i][j][q] = 0.0f;

    auto load_stage = [&](int s, int kt) {
        uint32_t sAh = sb + s * GS_STAGE;
        uint32_t sAl = sAh + 16384;
        uint32_t sB  = sAh + 32768;
#pragma unroll
        for (int i = 0; i < 4; i++) {
            int idx = tid + (i << 8);
            int row = idx >> 3, c = idx & 7;
            uint32_t soff = (uint32_t)(row << 7) + (((uint32_t)(c ^ (row & 7))) << 4);
            const __half* ar = Ab + (size_t)row * KP + kt * 64 + c * 8;
            CPA16(sAh + soff, (const char*)ar);
            CPA16(sAl + soff, (const char*)(ar + 2048));
            CPA16(sB + soff, (const char*)(Bb + (size_t)row * 2048 + kt * 64 + c * 8));
        }
        CPA_COMMIT();
    };

    load_stage(0, 0);
    const int lr15 = lane & 15, lhi = lane >> 4;

    for (int kt = 0; kt < GKSTEPS; kt++) {
        int s = kt & 1;
        if (kt + 1 < GKSTEPS) {
            load_stage(s ^ 1, kt + 1);
            asm volatile("cp.async.wait_group 1;" ::: "memory");
        } else {
            CPA_WAIT0();
        }
        __syncthreads();

        uint32_t aH = sb + s * GS_STAGE;
        uint32_t aL = aH + 16384;
        uint32_t bB = aH + 32768;
#pragma unroll
        for (int ks = 0; ks < 4; ks++) {
            uint32_t bf[4][2];
#pragma unroll
            for (int np = 0; np < 2; np++) {
                int row = nw + np * 16 + lr15;
                uint32_t bd = bB + (uint32_t)(row << 7) + ((uint32_t)((2 * ks + lhi) ^ (row & 7)) << 4);
                uint32_t r0, r1, r2, r3;
                ldsm_x4(bd, r0, r1, r2, r3);
                bf[np * 2][0] = r0;     bf[np * 2][1] = r2;
                bf[np * 2 + 1][0] = r1; bf[np * 2 + 1][1] = r3;
            }
            uint32_t af[4][4];
#pragma unroll
            for (int mt = 0; mt < 4; mt++) {
                int row = mw + mt * 16 + lr15;
                uint32_t ad = aH + (uint32_t)(row << 7) + ((uint32_t)((2 * ks + lhi) ^ (row & 7)) << 4);
                ldsm_x4(ad, af[mt][0], af[mt][1], af[mt][2], af[mt][3]);
            }
#pragma unroll
            for (int mt = 0; mt < 4; mt++)
#pragma unroll
                for (int nt = 0; nt < 4; nt++)
                    mma_f16(acc[mt][nt], af[mt], bf[nt]);
#pragma unroll
            for (int mt = 0; mt < 4; mt++) {
                int row = mw + mt * 16 + lr15;
                uint32_t ad = aL + (uint32_t)(row << 7) + ((uint32_t)((2 * ks + lhi) ^ (row & 7)) << 4);
                ldsm_x4(ad, af[mt][0], af[mt][1], af[mt][2], af[mt][3]);
            }
#pragma unroll
            for (int mt = 0; mt < 4; mt++)
#pragma unroll
                for (int nt = 0; nt < 4; nt++)
                    mma_f16(acc[mt][nt], af[mt], bf[nt]);
        }
        __syncthreads();
    }

#pragma unroll
    for (int mt = 0; mt < 4; mt++) {
#pragma unroll
        for (int nt = 0; nt < 4; nt++) {
            int col = n0 + nw + nt * 8 + (lane & 3) * 2;
            int row = m0 + mw + mt * 16 + (lane >> 2);
            float2 va = make_float2(acc[mt][nt][0], acc[mt][nt][1]);
            float2 vb = make_float2(acc[mt][nt][2], acc[mt][nt][3]);
            if (!fused) {
                *(float2*)(Cext + (size_t)row * 2048 + col) = va;
                *(float2*)(Cext + (size_t)(row + 8) * 2048 + col) = vb;
            } else if (col < 2048) {
                *(float2*)(g_xq + (size_t)row * 2048 + col) = va;
                *(float2*)(g_xq + (size_t)(row + 8) * 2048 + col) = vb;
            } else if (col < 4096) {
                *(float2*)(g_xv + (size_t)row * 2048 + col - 2048) = va;
                *(float2*)(g_xv + (size_t)(row + 8) * 2048 + col - 2048) = vb;
            } else if (col < 4128) {
                *(float2*)(g_lrraw + (size_t)row * 32 + col - 4096) = va;
                *(float2*)(g_lrraw + (size_t)(row + 8) * 32 + col - 4096) = vb;
            }
        }
    }
}

// ---------------- TTT scan: register LN via half-warp shuffles, no z smem ----------------
__global__ __launch_bounds__(256) void ttt_scan_kernel(
    const float* __restrict__ lt_idx,
    const float* __restrict__ lnw_g, const float* __restrict__ lnb_g,
    const float* __restrict__ W1g,   const float* __restrict__ b1g,
    const float* __restrict__ cqw,   const float* __restrict__ cqb,
    const float* __restrict__ ckw,   const float* __restrict__ ckb,
    const float* __restrict__ lrb)
{
    __shared__ float W1[64][64];
    __shared__ float sraw[2][19][68];
    __shared__ float sxv[2][16][68];
    __shared__ float sxq[16][68], sxk[16][68];
    __shared__ float grad[16][68];
    __shared__ float attn[16][16];
    __shared__ float wq_s[256], wk_s[256];
    __shared__ float bq_s[64], bk_s[64];
    __shared__ float b1[64], lnw[64], lnb[64];
    __shared__ float lrrawbuf[2][16], lr_sh[16], tok[16];

    int tid = threadIdx.x;
    int b = blockIdx.x >> 5, h = blockIdx.x & 31;
    const int ch0 = h * 64;

    for (int o = tid; o < 4096; o += 256)
        ((float*)W1)[o] = W1g[(size_t)h * 4096 + o];
    if (tid < 64) {
        b1[tid]  = b1g[h * 64 + tid];
        lnw[tid] = lnw_g[h * 64 + tid];
        lnb[tid] = lnb_g[h * 64 + tid];
        bq_s[tid] = cqb[ch0 + tid];
        bk_s[tid] = ckb[ch0 + tid];
    }
    wq_s[tid] = cqw[ch0 * 4 + tid];
    wk_s[tid] = ckw[ch0 * 4 + tid];
    if (tid < 16) tok[tid] = fmaxf(1.0f / (float)(tid + 1) + lt_idx[tid], 0.0f);
    for (int o = tid; o < 2 * 19 * 68; o += 256)
        ((float*)sraw)[o] = 0.0f;

    const int ii = tid >> 4;
    const int d0 = (tid & 15) * 4;
    const size_t base = ((size_t)b * LZ) * WD + (size_t)ch0;
    const float lrb_h = lrb[h];

    float cs0, sn0, cs1, sn1;
    {
        int i0 = d0 >> 1;
        float inv0 = exp2f(-(float)i0 * (13.2877123795f / 32.0f));
        float inv1 = exp2f(-(float)(i0 + 1) * (13.2877123795f / 32.0f));
        sincosf((float)ii * inv0, &sn0, &cs0);
        sincosf((float)ii * inv1, &sn1, &cs1);
    }
    __syncthreads();

    // loop-invariant per-thread registers
    const float4 lnw4 = *(const float4*)&lnw[d0];
    const float4 lnb4 = *(const float4*)&lnb[d0];
    const float tok_ii = tok[ii];
    const float te = tok[15];

    const uint32_t a_raw = smem_u32(&sraw[0][0][0]);
    const uint32_t a_xv  = smem_u32(&sxv[0][0][0]);
    const uint32_t a_lrr = smem_u32(&lrrawbuf[0][0]);
    const uint32_t RAWB = 19 * 68 * 4;
    const uint32_t XVB  = 16 * 68 * 4;

    auto prefetch = [&](int s, int n) {
#pragma unroll
        for (int it = 0; it < 2; it++) {
            int idx = tid + (it << 8);
            if (idx < 304) {
                int row = idx >> 4, c = idx & 15;
                int g = n * MBSZ - 3 + row;
                if (g >= 0)
                    CPA16(a_raw + s * RAWB + (uint32_t)(row * 272 + c * 16),
                          (const char*)&g_xq[base + (size_t)g * WD + c * 4]);
            }
        }
        {
            int row = tid >> 4, c = tid & 15;
            CPA16(a_xv + s * XVB + (uint32_t)(row * 272 + c * 16),
                  (const char*)&g_xv[base + (size_t)(n * MBSZ + row) * WD + c * 4]);
        }
        if (tid < 16)
            CPA4(a_lrr + s * 64 + tid * 4,
                 (const char*)&g_lrraw[((size_t)b * LZ + n * MBSZ + tid) * 32 + h]);
        CPA_COMMIT();
    };

    prefetch(0, 0);

    for (int n = 0; n < NMBC; n++) {
        const int s = n & 1;
        CPA_WAIT0();
        __syncthreads();
        if (n + 1 < NMBC) prefetch(s ^ 1, n + 1);

        // conv + rope; keep oq/ok in registers, also store to smem for attn/W1-update
        float4 oq, ok;
        {
            float4 t0 = *(const float4*)&sraw[s][ii + 0][d0];
            float4 t1 = *(const float4*)&sraw[s][ii + 1][d0];
            float4 t2 = *(const float4*)&sraw[s][ii + 2][d0];
            float4 t3 = *(const float4*)&sraw[s][ii + 3][d0];
            const float* ta = (const float*)&t0;
            const float* tb = (const float*)&t1;
            const float* tc = (const float*)&t2;
            const float* td = (const float*)&t3;
            float qv[4], kv[4];
#pragma unroll
            for (int d = 0; d < 4; d++) {
                int ch = d0 + d;
                qv[d] = bq_s[ch] + ta[d] * wq_s[ch * 4] + tb[d] * wq_s[ch * 4 + 1]
                                 + tc[d] * wq_s[ch * 4 + 2] + td[d] * wq_s[ch * 4 + 3];
                kv[d] = bk_s[ch] + ta[d] * wk_s[ch * 4] + tb[d] * wk_s[ch * 4 + 1]
                                 + tc[d] * wk_s[ch * 4 + 2] + td[d] * wk_s[ch * 4 + 3];
            }
            oq.x = qv[0] * cs0 - qv[1] * sn0;  oq.y = qv[1] * cs0 + qv[0] * sn0;
            oq.z = qv[2] * cs1 - qv[3] * sn1;  oq.w = qv[3] * cs1 + qv[2] * sn1;
            ok.x = kv[0] * cs0 - kv[1] * sn0;  ok.y = kv[1] * cs0 + kv[0] * sn0;
            ok.z = kv[2] * cs1 - kv[3] * sn1;  ok.w = kv[3] * cs1 + kv[2] * sn1;
            *(float4*)&sxq[ii][d0] = oq;
            *(float4*)&sxk[ii][d0] = ok;
        }
        if (tid < 16)
            lr_sh[tid] = (1.0f / 64.0f) / (1.0f + expf(-(lrrawbuf[s][tid] + lrb_h)));
        __syncthreads();

        // merged dual matmul: acck = xk@W1+b1, accq = xq@W1+b1 (registers)
        float4 acck = *(const float4*)&b1[d0];
        float4 accq = acck;
#pragma unroll
        for (int e4 = 0; e4 < 16; e4++) {
            float4 xk4 = *(const float4*)&sxk[ii][e4 * 4];
            float4 xq4 = *(const float4*)&sxq[ii][e4 * 4];
            float4 w;
            w = *(const float4*)&W1[e4 * 4 + 0][d0];
            acck.x += xk4.x * w.x; acck.y += xk4.x * w.y; acck.z += xk4.x * w.z; acck.w += xk4.x * w.w;
            accq.x += xq4.x * w.x; accq.y += xq4.x * w.y; accq.z += xq4.x * w.z; accq.w += xq4.x * w.w;
            w = *(const float4*)&W1[e4 * 4 + 1][d0];
            acck.x += xk4.y * w.x; acck.y += xk4.y * w.y; acck.z += xk4.y * w.z; acck.w += xk4.y * w.w;
            accq.x += xq4.y * w.x; accq.y += xq4.y * w.y; accq.z += xq4.y * w.z; accq.w += xq4.y * w.w;
            w = *(const float4*)&W1[e4 * 4 + 2][d0];
            acck.x += xk4.z * w.x; acck.y += xk4.z * w.y; acck.z += xk4.z * w.z; acck.w += xk4.z * w.w;
            accq.x += xq4.z * w.x; accq.y += xq4.z * w.y; accq.z += xq4.z * w.z; accq.w += xq4.z * w.w;
            w = *(const float4*)&W1[e4 * 4 + 3][d0];
            acck.x += xk4.w * w.x; acck.y += xk4.w * w.y; acck.z += xk4.w * w.z; acck.w += xk4.w * w.w;
            accq.x += xq4.w * w.x; accq.y += xq4.w * w.y; accq.z += xq4.w * w.z; accq.w += xq4.w * w.w;
        }
        // attn (float4 dot)
        {
            int i = tid >> 4, j = tid & 15;
            const float4* qa = (const float4*)&sxq[i][0];
            const float4* ka = (const float4*)&sxk[j][0];
            float sa = 0.0f;
#pragma unroll
            for (int d4 = 0; d4 < 16; d4++) {
                float4 a = qa[d4], c = ka[d4];
                sa += a.x * c.x + a.y * c.y + a.z * c.z + a.w * c.w;
            }
            attn[i][j] = sa;
        }

        // grad = ln_l2_bwd(acck, xv - xk): half-warp (16-lane) shuffles on registers
        {
            float sm = acck.x + acck.y + acck.z + acck.w;
            float qq = acck.x * acck.x + acck.y * acck.y + acck.z * acck.z + acck.w * acck.w;
#pragma unroll
            for (int o = 8; o; o >>= 1) {
                sm += __shfl_xor_sync(0xffffffffu, sm, o);
                qq += __shfl_xor_sync(0xffffffffu, qq, o);
            }
            float mu = sm * (1.0f / 64.0f);
            float rstd = rsqrtf(fmaxf(qq * (1.0f / 64.0f) - mu * mu, 0.0f) + EPSC);
            float4 xv4 = *(const float4*)&sxv[s][ii][d0];
            float4 xh, gy;
            xh.x = (acck.x - mu) * rstd; xh.y = (acck.y - mu) * rstd;
            xh.z = (acck.z - mu) * rstd; xh.w = (acck.w - mu) * rstd;
            gy.x = (lnw4.x * xh.x + lnb4.x - (xv4.x - ok.x)) * lnw4.x;
            gy.y = (lnw4.y * xh.y + lnb4.y - (xv4.y - ok.y)) * lnw4.y;
            gy.z = (lnw4.z * xh.z + lnb4.z - (xv4.z - ok.z)) * lnw4.z;
            gy.w = (lnw4.w * xh.w + lnb4.w - (xv4.w - ok.w)) * lnw4.w;
            float u1 = gy.x + gy.y + gy.z + gy.w;
            float u2 = gy.x * xh.x + gy.y * xh.y + gy.z * xh.z + gy.w * xh.w;
#pragma unroll
            for (int o = 8; o; o >>= 1) {
                u1 += __shfl_xor_sync(0xffffffffu, u1, o);
                u2 += __shfl_xor_sync(0xffffffffu, u2, o);
            }
            float sc = rstd * (1.0f / 64.0f);
            float4 gr;
            gr.x = (64.0f * gy.x - u1 - xh.x * u2) * sc;
            gr.y = (64.0f * gy.y - u1 - xh.y * u2) * sc;
            gr.z = (64.0f * gy.z - u1 - xh.z * u2) * sc;
            gr.w = (64.0f * gy.w - u1 - xh.w * u2) * sc;
            *(float4*)&grad[ii][d0] = gr;
        }
        __syncthreads();

        // Z1_bar correction + inline output LN
        {
            for (int j = 0; j <= ii; j++) {
                float cf = tok_ii * lr_sh[j] * (attn[ii][j] + 1.0f);
                float4 gr = *(const float4*)&grad[j][d0];
                accq.x -= cf * gr.x; accq.y -= cf * gr.y; accq.z -= cf * gr.z; accq.w -= cf * gr.w;
            }
            float sm = accq.x + accq.y + accq.z + accq.w;
            float qq = accq.x * accq.x + accq.y * accq.y + accq.z * accq.z + accq.w * accq.w;
#pragma unroll
            for (int o = 8; o; o >>= 1) {
                sm += __shfl_xor_sync(0xffffffffu, sm, o);
                qq += __shfl_xor_sync(0xffffffffu, qq, o);
            }
            float mu = sm * (1.0f / 64.0f);
            float rstd = rsqrtf(fmaxf(qq * (1.0f / 64.0f) - mu * mu, 0.0f) + EPSC);
            float4 outv;
            outv.x = oq.x + lnw4.x * ((accq.x - mu) * rstd) + lnb4.x;
            outv.y = oq.y + lnw4.y * ((accq.y - mu) * rstd) + lnb4.y;
            outv.z = oq.z + lnw4.z * ((accq.z - mu) * rstd) + lnb4.z;
            outv.w = oq.w + lnw4.w * ((accq.w - mu) * rstd) + lnb4.w;
            *(float4*)&g_scan[base + (size_t)(n * MBSZ + ii) * WD + d0] = outv;
        }

        // W1 update: 4 row-accumulators, single pass over j
        {
            int dr = ii * 4;
            float4 acc0 = *(const float4*)&W1[dr + 0][d0];
            float4 acc1 = *(const float4*)&W1[dr + 1][d0];
            float4 acc2 = *(const float4*)&W1[dr + 2][d0];
            float4 acc3 = *(const float4*)&W1[dr + 3][d0];
#pragma unroll
            for (int j = 0; j < 16; j++) {
                float lj = te * lr_sh[j];
                float4 gr  = *(const float4*)&grad[j][d0];
                float4 xk4 = *(const float4*)&sxk[j][dr];
                float c0 = lj * xk4.x, c1 = lj * xk4.y, c2 = lj * xk4.z, c3 = lj * xk4.w;
                acc0.x -= c0 * gr.x; acc0.y -= c0 * gr.y; acc0.z -= c0 * gr.z; acc0.w -= c0 * gr.w;
                acc1.x -= c1 * gr.x; acc1.y -= c1 * gr.y; acc1.z -= c1 * gr.z; acc1.w -= c1 * gr.w;
                acc2.x -= c2 * gr.x; acc2.y -= c2 * gr.y; acc2.z -= c2 * gr.z; acc2.w -= c2 * gr.w;
                acc3.x -= c3 * gr.x; acc3.y -= c3 * gr.y; acc3.z -= c3 * gr.z; acc3.w -= c3 * gr.w;
            }
            *(float4*)&W1[dr + 0][d0] = acc0;
            *(float4*)&W1[dr + 1][d0] = acc1;
            *(float4*)&W1[dr + 2][d0] = acc2;
            *(float4*)&W1[dr + 3][d0] = acc3;
            if (tid < 64) {
                float sm = 0.0f;
#pragma unroll
                for (int j = 0; j < 16; j++) sm += lr_sh[j] * grad[j][tid];
                b1[tid] -= te * sm;
            }
        }
        __syncthreads();
    }
}

// ---------------- post layer-norm fused with A split-fp16 conversion ----------------
__global__ __launch_bounds__(256) void ttt_postnorm_cvt(
    const float* __restrict__ pw, const float* __restrict__ pb)
{
    __shared__ float red[8];
    int bl = blockIdx.x, tid = threadIdx.x;
    int lane = tid & 31, warp = tid >> 5;
    const float4* src = (const float4*)(g_scan + (size_t)bl * WD);
    float4 v0 = src[tid], v1 = src[tid + 256];

    float s = v0.x + v0.y + v0.z + v0.w + v1.x + v1.y + v1.z + v1.w;
#pragma unroll
    for (int o = 16; o; o >>= 1) s += __shfl_xor_sync(0xffffffffu, s, o);
    if (lane == 0) red[warp] = s;
    __syncthreads();
    float tot = 0.0f;
#pragma unroll
    for (int i = 0; i < 8; i++) tot += red[i];
    float mu = tot * (1.0f / 2048.0f);
    __syncthreads();

    float q =
        (v0.x - mu) * (v0.x - mu) + (v0.y - mu) * (v0.y - mu) +
        (v0.z - mu) * (v0.z - mu) + (v0.w - mu) * (v0.w - mu) +
        (v1.x - mu) * (v1.x - mu) + (v1.y - mu) * (v1.y - mu) +
        (v1.z - mu) * (v1.z - mu) + (v1.w - mu) * (v1.w - mu);
#pragma unroll
    for (int o = 16; o; o >>= 1) q += __shfl_xor_sync(0xffffffffu, q, o);
    if (lane == 0) red[warp] = q;
    __syncthreads();
    float qt = 0.0f;
#pragma unroll
    for (int i = 0; i < 8; i++) qt += red[i];
    float rstd = rsqrtf(qt * (1.0f / 2048.0f) + EPSC);

    float4 w0 = ((const float4*)pw)[tid], w1 = ((const float4*)pw)[tid + 256];
    float4 b0 = ((const float4*)pb)[tid], b1v = ((const float4*)pb)[tid + 256];
    float4 o0, o1;
    o0.x = (v0.x - mu) * rstd * w0.x + b0.x;
    o0.y = (v0.y - mu) * rstd * w0.y + b0.y;
    o0.z = (v0.z - mu) * rstd * w0.z + b0.z;
    o0.w = (v0.w - mu) * rstd * w0.w + b0.w;
    o1.x = (v1.x - mu) * rstd * w1.x + b1v.x;
    o1.y = (v1.y - mu) * rstd * w1.y + b1v.y;
    o1.z = (v1.z - mu) * rstd * w1.z + b1v.z;
    o1.w = (v1.w - mu) * rstd * w1.w + b1v.w;

    size_t base0 = (size_t)bl * KP + (tid << 2);
    size_t base1 = (size_t)bl * KP + ((tid + 256) << 2);
    uint2 hi, lo;
    splitf16(o0, hi, lo);
    *(uint2*)(g_A_hf + base0)        = hi;
    *(uint2*)(g_A_hf + base0 + 2048) = lo;
    splitf16(o1, hi, lo);
    *(uint2*)(g_A_hf + base1)        = hi;
    *(uint2*)(g_A_hf + base1 + 2048) = lo;
}

// ---------------- launcher ----------------
extern "C" void kernel_launch(void* const* d_in, const int* in_sizes, int n_in,
                              void* d_out, int out_size)
{
    const float* hs  = (const float*)d_in[0];
    const float* q_w = (const float*)d_in[1];
    const float* v_w = (const float*)d_in[2];
    const float* o_w = (const float*)d_in[3];
    const float* cqw = (const float*)d_in[4];
    const float* cqb = (const float*)d_in[5];
    const float* ckw = (const float*)d_in[6];
    const float* ckb = (const float*)d_in[7];
    const float* lrw = (const float*)d_in[8];
    const float* lrb = (const float*)d_in[9];
    const float* lti = (const float*)d_in[10];
    const float* tnw = (const float*)d_in[11];
    const float* tnb = (const float*)d_in[12];
    const float* W1i = (const float*)d_in[13];
    const float* b1i = (const float*)d_in[14];
    const float* pnw = (const float*)d_in[15];
    const float* pnb = (const float*)d_in[16];
    float* out = (float*)d_out;

    static int smem_set = 0;
    if (!smem_set) {
        cudaFuncSetAttribute(ttt_hgemm, cudaFuncAttributeMaxDynamicSharedMemorySize, 2 * GS_STAGE);
        smem_set = 1;
    }

    // fused QV+lr projection: A=hs, B=[q_w; v_w; lr_w; pad]
    ttt_cvtA<<<16384, 256>>>(hs);
    ttt_cvtB<<<NROWS_B, 256>>>(q_w, v_w, lrw);
    ttt_hgemm<<<dim3(33, 64), 256, 2 * GS_STAGE>>>(nullptr, 1);   // -> g_xq, g_xv, g_lrraw

    // scan (conv+rope+lr fused inside)
    ttt_scan_kernel<<<BZ * NHD, 256>>>(lti, tnw, tnb, W1i, b1i, cqw, cqb, ckw, ckb, lrb);

    // B for final GEMM (stream-ordered after GEMM1 read g_B_hf)
    ttt_cvtB<<<2048, 256>>>(o_w, o_w, o_w);
    ttt_postnorm_cvt<<<BZ * LZ, 256>>>(pnw, pnb);                 // -> g_A_hf

    ttt_hgemm<<<dim3(16, 64), 256, 2 * GS_STAGE>>>(out, 0);
}